// round 12
// baseline (speedup 1.0000x reference)
#include <cuda_runtime.h>
#include <cuda_bf16.h>
#include <cuda_fp16.h>
#include <cstdint>

#define T 8
#define V 10000
#define E 100000
#define C_IN 128
#define H 256
#define DS 16
#define C_OUT 64
#define HD (H * DS)          // 4096
#define TV (T * V)           // 80000

// ---------------------------------------------------------------------------
// Scratch (device globals; no allocation allowed)
// ---------------------------------------------------------------------------
__device__ __align__(128) float g_x0[(size_t)TV * C_IN];
__device__ __align__(128) float g_x1[(size_t)TV * H];
__device__ __align__(128) float g_hT[(size_t)H * TV];   // sage output, [hh][t][v]
__device__ __align__(128) float g_xsr[(size_t)TV * H];
__device__ __align__(128) float g_agg[(size_t)TV * H];
__device__ __align__(128) float g_deg[(size_t)TV];
__device__ __align__(128) float g_lam[2 * HD];
__device__ __align__(128) float g_xlast[(size_t)V * H];
__device__ __align__(128) float g_xsrl [(size_t)V * H];
__device__ int g_is64;

// fp16 single-plane transposed weights ([N=256][K], K-major)
__device__ __align__(128) __half g_cat0_f[256 * 256];
__device__ __align__(128) __half g_cat1_f[256 * 512];
__device__ __align__(128) __half g_res0_f[256 * 128];
__device__ __align__(128) __half g_res1_f[256 * 256];
__device__ __align__(128) __half g_mix0_f[256 * HD];
__device__ __align__(128) __half g_mix1_f[256 * HD];

// ---------------------------------------------------------------------------
// Helpers
// ---------------------------------------------------------------------------
__device__ __forceinline__ uint32_t smem_u32(const void* p) {
    uint32_t a;
    asm("{ .reg .u64 t; cvta.to.shared.u64 t, %1; cvt.u32.u64 %0, t; }" : "=r"(a) : "l"(p));
    return a;
}

__device__ __forceinline__ uint32_t pack2h(float a, float b) {
    __half h0 = __float2half_rn(a);
    __half h1 = __float2half_rn(b);
    return (uint32_t)__half_as_ushort(h0) | ((uint32_t)__half_as_ushort(h1) << 16);
}

__device__ __forceinline__ void f16_split(float x, __half& h_, __half& l_) {
    h_ = __float2half_rn(x);
    l_ = __float2half_rn(x - __half2float(h_));
}

#define LDSM_X4(r0, r1, r2, r3, addr) \
    asm volatile("ldmatrix.sync.aligned.m8n8.x4.shared.b16 {%0,%1,%2,%3}, [%4];" \
        : "=r"(r0), "=r"(r1), "=r"(r2), "=r"(r3) : "r"(addr))

#define MMA_F16(d, a, b0, b1) \
    asm volatile("mma.sync.aligned.m16n8k16.row.col.f32.f16.f16.f32 " \
        "{%0,%1,%2,%3}, {%4,%5,%6,%7}, {%8,%9}, {%0,%1,%2,%3};" \
        : "+f"((d)[0]), "+f"((d)[1]), "+f"((d)[2]), "+f"((d)[3]) \
        : "r"((a)[0]), "r"((a)[1]), "r"((a)[2]), "r"((a)[3]), "r"(b0), "r"(b1))

#define CP16(dst, src) \
    asm volatile("cp.async.cg.shared.global [%0], [%1], 16;" :: "r"(dst), "l"(src))
#define CP_COMMIT() asm volatile("cp.async.commit_group;" ::: "memory")
#define CP_WAIT0()  asm volatile("cp.async.wait_group 0;" ::: "memory")

// ---------------------------------------------------------------------------
// Small kernels
// ---------------------------------------------------------------------------
__global__ void zero_kernel(float4* p, long long n4) {
    long long i = blockIdx.x * (long long)blockDim.x + threadIdx.x;
    long long stride = (long long)gridDim.x * blockDim.x;
    for (; i < n4; i += stride) p[i] = make_float4(0.f, 0.f, 0.f, 0.f);
}

__global__ void detect_kernel(const unsigned int* ei) {
    if (threadIdx.x == 0 && blockIdx.x == 0) {
        unsigned int s = 0;
        for (int i = 0; i < 64; i++) s |= ei[2 * i + 1];
        g_is64 = (s == 0) ? 1 : 0;
    }
}

__device__ __forceinline__ int load_edge(const void* ei, long long pos) {
    if (g_is64) return (int)((const long long*)ei)[pos];
    return ((const int*)ei)[pos];
}

__global__ void lam_kernel(const float* a0, const float* a1, float* lam) {
    int i = blockIdx.x * blockDim.x + threadIdx.x;
    if (i < HD)           lam[i] = expf(-expf(a0[i]));
    else if (i < 2 * HD)  lam[i] = expf(-expf(a1[i - HD]));
}

__global__ void token_mix_kernel(const float* __restrict__ xs,
                                 const float* __restrict__ w,
                                 const float* __restrict__ b,
                                 float* __restrict__ out) {
    int idx = blockIdx.x * blockDim.x + threadIdx.x;
    if (idx >= TV * C_IN) return;
    int c = idx % C_IN;
    int t = idx / (V * C_IN);
    float acc = b[c] + xs[idx] * w[c * 3 + 1];
    if (t > 0)     acc += xs[idx - V * C_IN] * w[c * 3 + 0];
    if (t < T - 1) acc += xs[idx + V * C_IN] * w[c * 3 + 2];
    out[idx] = acc;
}

// scatter with fused degree accumulation (c4 == 0 lane adds 1 to deg)
__global__ void scatter_kernel(const float* __restrict__ x, const void* __restrict__ ei,
                               float* __restrict__ agg, float* __restrict__ deg, int C) {
    int chunks = C >> 2;
    long long idx = blockIdx.x * (long long)blockDim.x + threadIdx.x;
    long long total = (long long)T * E * chunks;
    if (idx >= total) return;
    int c4 = (int)(idx % chunks);
    long long te = idx / chunks;
    int e = (int)(te % E);
    int t = (int)(te / E);
    long long base = (long long)t * 2 * E;
    int src = load_edge(ei, base + e);
    int dst = load_edge(ei, base + E + e);
    float4 v = *(const float4*)&x[((long long)t * V + src) * C + c4 * 4];
    float* p = &agg[((long long)t * V + dst) * C + c4 * 4];
    asm volatile("red.global.add.v4.f32 [%0], {%1,%2,%3,%4};"
                 :: "l"(p), "f"(v.x), "f"(v.y), "f"(v.z), "f"(v.w) : "memory");
    if (deg && c4 == 0) {
        float* dp = &deg[(long long)t * V + dst];
        asm volatile("red.global.add.f32 [%0], %1;" :: "l"(dp), "f"(1.0f) : "memory");
    }
}

// Build transposed fp16 weights: dst[n][k] = rn(concat(w1,w2)[k][n])
__global__ void f16w_kernel(const float* __restrict__ w1, const float* __restrict__ w2,
                            int K1, int Kt, __half* __restrict__ out) {
    long long idx = blockIdx.x * (long long)blockDim.x + threadIdx.x;
    if (idx >= (long long)Kt * 256) return;
    int k = (int)(idx % Kt);
    int n = (int)(idx / Kt);
    float v = (k < K1) ? w1[(long long)k * 256 + n] : w2[(long long)(k - K1) * 256 + n];
    out[(long long)n * Kt + k] = __float2half_rn(v);
}

// ---------------------------------------------------------------------------
// fp16 tensor GEMM, tile 64x128, BK=64, 256 threads (8 warps 2m x 4n, warp
// tile 32x32), 2 CTAs/SM, double-buffered SMEM, cp.async B (single fp16 plane).
//   MODE 0 (scan-fused z-PAIR): one CTA computes timesteps t0=2z and t0+1.
//       Plane 0: A = rn16(relu(scan to ts0));  Plane 1: one extra scan step.
//       lam/Bp preloaded in SMEM; hT read once for both planes.
//   MODE 1 (cat, 2-product): A = concat(A1, A2*invdeg) fp32 -> fp16 hi/lo.
// ---------------------------------------------------------------------------
#define ROWB 144                      // 64 k * 2B + 16 pad
#define AH_T 9216                     // 64 * 144
#define BH_T 18432                    // 128 * 144
#define STG_M0 (2 * AH_T + BH_T)      // 36864 (two A planes + B)
#define STG_M1 (2 * AH_T + BH_T)      // 36864 (A hi/lo + B)
#define LAM_OFF (2 * STG_M0)          // 73728
#define GS_M0 (2 * STG_M0 + 32768)    // 106496 (lam 16K + Bp 16K)
#define GS_M1 (2 * STG_M1)            // 73728

template <int MODE>
__global__ __launch_bounds__(256, 2) void mgemm_kernel(
    const float* __restrict__ A1, const float* __restrict__ A2, int K1,
    const float* __restrict__ deg,
    const float* __restrict__ hT, const float* __restrict__ lam,
    const float* __restrict__ Bp, int tfix,
    const __half* __restrict__ Bf,
    const float* __restrict__ bias,
    const float* __restrict__ Dadd, long long DzS,
    float* __restrict__ Cout, long long CzS, long long CtS, int trans_out,
    int M, int K)
{
    constexpr int STG = (MODE == 0) ? STG_M0 : STG_M1;
    constexpr int B_OFF = 2 * AH_T;
    extern __shared__ char smem[];
    const uint32_t sb = smem_u32(smem);
    const int tid = threadIdx.x;
    const int wid = tid >> 5;
    const int lane = tid & 31;
    const int warp_m = wid >> 2;       // 0..1
    const int warp_n = wid & 3;        // 0..3
    const int z = blockIdx.z;
    const long long m0 = (long long)blockIdx.x * 64;
    const int n0 = blockIdx.y * 128;

    // MODE 0 pair setup
    const int t0  = (MODE == 0) ? (tfix > 0 ? 0 : 2 * z) : 0;
    const int ts0 = (MODE == 0) ? (tfix > 0 ? tfix : 2 * z + 1) : 0;
    const bool act1 = (MODE == 0) && (tfix == 0);
    const int tsmax = act1 ? ts0 + 1 : ts0;

    // acc[plane][i][j][4]; MODE 1 uses plane 0 only for output (plane1 = lo-A partial)
    float acc[2][2][4][4];
#pragma unroll
    for (int p = 0; p < 2; p++)
#pragma unroll
        for (int i = 0; i < 2; i++)
#pragma unroll
            for (int j = 0; j < 4; j++)
#pragma unroll
                for (int q2 = 0; q2 < 4; q2++) acc[p][i][j][q2] = 0.f;

    const int nK = K / 64;

    // producer coords: q = 16-k segment (0..3), r = row (0..63)
    const int q = tid >> 6;
    const int r = tid & 63;
    const long long rg1 = m0 + r;
    const bool rowok = (rg1 < M);

    float a16[16];                     // MODE 1 staging
    float hx[8];                       // MODE 0 staging (one hh column)

    const uint32_t aoff = (uint32_t)(warp_m * 32 + (lane & 15)) * ROWB +
                          (uint32_t)((lane >> 4) << 3) * 2;
    const uint32_t boff = (uint32_t)(warp_n * 32 + ((lane >> 4) << 3) + (lane & 7)) * ROWB +
                          (uint32_t)(((lane >> 3) & 1) << 3) * 2;

    if (MODE == 0) {
#pragma unroll
        for (int j = 0; j < 4; j++) {
            int idx = tid + 256 * j;
            *(float4*)(smem + LAM_OFF + idx * 16)         = ((const float4*)lam)[idx];
            *(float4*)(smem + LAM_OFF + 16384 + idx * 16) = ((const float4*)Bp)[idx];
        }
    }

    auto cpB = [&](int kt, int stage) {
        const int k0 = kt * 64;
        const uint32_t base = sb + stage * STG + B_OFF;
#pragma unroll
        for (int i = 0; i < 4; i++) {
            int idx = tid + 256 * i;
            int n  = idx >> 3;
            int kq = idx & 7;
            uint32_t dst = base + (uint32_t)n * ROWB + (uint32_t)kq * 16;
            long long soff = (long long)(n0 + n) * K + k0 + kq * 8;
            CP16(dst, Bf + soff);
        }
    };

    auto prefA = [&](int kt) {
        const int kg = kt * 64 + q * 16;
        if (MODE == 0) {
            const int hh = kg >> 4;
            const long long hb = (long long)hh * TV + rg1;
#pragma unroll
            for (int tt = 0; tt < 8; tt++)
                hx[tt] = (rowok && tt < tsmax) ? hT[hb + (long long)tt * V] : 0.f;
        } else {
            if (rowok) {
                bool second = (kg >= K1);
                const float* src = second ? &A2[rg1 * (long long)(K - K1) + (kg - K1)]
                                          : &A1[rg1 * (long long)K1 + kg];
#pragma unroll
                for (int f = 0; f < 4; f++)
                    *(float4*)&a16[f * 4] = ((const float4*)src)[f];
                if (second && deg) {
                    float inv = 1.0f / fmaxf(deg[rg1], 1.0f);
#pragma unroll
                    for (int d = 0; d < 16; d++) a16[d] *= inv;
                }
            } else {
#pragma unroll
                for (int d = 0; d < 16; d++) a16[d] = 0.f;
            }
        }
    };

    auto produceA = [&](int stage, int kt) {
        const uint32_t off = (uint32_t)stage * STG + (uint32_t)r * ROWB + (uint32_t)q * 32;
        if (MODE == 0) {
            const int kg = kt * 64 + q * 16;
            // process two 8-k halves to limit register temps
#pragma unroll
            for (int h2 = 0; h2 < 2; h2++) {
                float lam8[8], b8[8], s[8];
                const int kb = (kg + h2 * 8) * 4;
                *(float4*)&lam8[0] = *(const float4*)(smem + LAM_OFF + kb);
                *(float4*)&lam8[4] = *(const float4*)(smem + LAM_OFF + kb + 16);
                *(float4*)&b8[0]   = *(const float4*)(smem + LAM_OFF + 16384 + kb);
                *(float4*)&b8[4]   = *(const float4*)(smem + LAM_OFF + 16384 + kb + 16);
#pragma unroll
                for (int d = 0; d < 8; d++) s[d] = 0.f;
#pragma unroll
                for (int tt = 0; tt < 8; tt++) {
                    if (tt < ts0) {
                        float x = hx[tt];
#pragma unroll
                        for (int d = 0; d < 8; d++) s[d] = lam8[d] * s[d] + x * b8[d];
                    }
                }
                uint32_t u[4];
#pragma unroll
                for (int d2 = 0; d2 < 4; d2++)
                    u[d2] = pack2h(fmaxf(s[d2 * 2], 0.f), fmaxf(s[d2 * 2 + 1], 0.f));
                *(uint4*)(smem + off + h2 * 16) = make_uint4(u[0], u[1], u[2], u[3]);
                if (act1) {
                    float x = hx[ts0];
#pragma unroll
                    for (int d = 0; d < 8; d++) s[d] = lam8[d] * s[d] + x * b8[d];
#pragma unroll
                    for (int d2 = 0; d2 < 4; d2++)
                        u[d2] = pack2h(fmaxf(s[d2 * 2], 0.f), fmaxf(s[d2 * 2 + 1], 0.f));
                    *(uint4*)(smem + off + AH_T + h2 * 16) = make_uint4(u[0], u[1], u[2], u[3]);
                }
            }
        } else {
            uint32_t uh[8], ul[8];
#pragma unroll
            for (int d2 = 0; d2 < 8; d2++) {
                __half h0, l0, h1, l1;
                f16_split(a16[d2 * 2 + 0], h0, l0);
                f16_split(a16[d2 * 2 + 1], h1, l1);
                uh[d2] = (uint32_t)__half_as_ushort(h0) |
                         ((uint32_t)__half_as_ushort(h1) << 16);
                ul[d2] = (uint32_t)__half_as_ushort(l0) |
                         ((uint32_t)__half_as_ushort(l1) << 16);
            }
            *(uint4*)(smem + off)             = make_uint4(uh[0], uh[1], uh[2], uh[3]);
            *(uint4*)(smem + off + 16)        = make_uint4(uh[4], uh[5], uh[6], uh[7]);
            *(uint4*)(smem + off + AH_T)      = make_uint4(ul[0], ul[1], ul[2], ul[3]);
            *(uint4*)(smem + off + AH_T + 16) = make_uint4(ul[4], ul[5], ul[6], ul[7]);
        }
    };

    auto compute = [&](int stage) {
        const uint32_t base = sb + stage * STG;
        const bool two = (MODE == 1) || act1;
#pragma unroll
        for (int ks = 0; ks < 4; ks++) {
            const uint32_t kk = (uint32_t)ks * 32;
            uint32_t b_h[8];
#pragma unroll
            for (int jj = 0; jj < 2; jj++) {
                uint32_t bd = base + B_OFF + boff + (uint32_t)(jj * 16) * ROWB + kk;
                LDSM_X4(b_h[jj * 4 + 0], b_h[jj * 4 + 1], b_h[jj * 4 + 2], b_h[jj * 4 + 3], bd);
            }
#pragma unroll
            for (int p = 0; p < 2; p++) {
                if (p == 1 && !two) break;
                uint32_t a_h[2][4];
#pragma unroll
                for (int i = 0; i < 2; i++) {
                    uint32_t ad = base + aoff + (uint32_t)(i * 16) * ROWB + kk + p * AH_T;
                    LDSM_X4(a_h[i][0], a_h[i][1], a_h[i][2], a_h[i][3], ad);
                }
#pragma unroll
                for (int i = 0; i < 2; i++)
#pragma unroll
                    for (int j = 0; j < 4; j++) {
                        // MODE 1: plane1 is the lo-A correction -> same acc
                        float* d = (MODE == 1) ? acc[0][i][j] : acc[p][i][j];
                        MMA_F16(d, a_h[i], b_h[j * 2], b_h[j * 2 + 1]);
                    }
            }
        }
    };

    // prologue
    prefA(0);
    cpB(0, 0);
    CP_COMMIT();
    if (MODE == 0) __syncthreads();
    produceA(0, 0);
    CP_WAIT0();
    __syncthreads();

    for (int kt = 0; kt < nK; kt++) {
        const int cur = kt & 1;
        const bool more = (kt + 1 < nK);
        if (more) {
            prefA(kt + 1);
            cpB(kt + 1, cur ^ 1);
            CP_COMMIT();
        }
        compute(cur);
        if (more) produceA(cur ^ 1, kt + 1);
        CP_WAIT0();
        __syncthreads();
    }

    // epilogue
    const int npl = (MODE == 0 && act1) ? 2 : 1;
#pragma unroll
    for (int p = 0; p < 2; p++) {
        if (p >= npl) break;
        const float* Dz = Dadd ? (Dadd + (long long)(t0 + p) * DzS) : (const float*)0;
        float* Cz = Cout + (long long)(t0 + p) * CzS;
#pragma unroll
        for (int i = 0; i < 2; i++) {
            long long r1 = m0 + warp_m * 32 + i * 16 + (lane >> 2);
            long long r2 = r1 + 8;
#pragma unroll
            for (int j = 0; j < 4; j++) {
                int c = n0 + warp_n * 32 + j * 8 + (lane & 3) * 2;
                float bx = 0.f, by = 0.f;
                if (bias) { float2 b2 = *(const float2*)&bias[c]; bx = b2.x; by = b2.y; }
                if (r1 < M) {
                    float vx = acc[p][i][j][0] + bx, vy = acc[p][i][j][1] + by;
                    if (Dz) { float2 d = *(const float2*)&Dz[r1 * 256 + c]; vx += d.x; vy += d.y; }
                    if (trans_out) {
                        Cz[(long long)c * CtS + r1]       = vx;
                        Cz[(long long)(c + 1) * CtS + r1] = vy;
                    } else {
                        *(float2*)&Cz[r1 * 256 + c] = make_float2(vx, vy);
                    }
                }
                if (r2 < M) {
                    float vx = acc[p][i][j][2] + bx, vy = acc[p][i][j][3] + by;
                    if (Dz) { float2 d = *(const float2*)&Dz[r2 * 256 + c]; vx += d.x; vy += d.y; }
                    if (trans_out) {
                        Cz[(long long)c * CtS + r2]       = vx;
                        Cz[(long long)(c + 1) * CtS + r2] = vy;
                    } else {
                        *(float2*)&Cz[r2 * 256 + c] = make_float2(vx, vy);
                    }
                }
            }
        }
    }
}

// ---------------------------------------------------------------------------
// fp32 SGEMM for the small output head (N=64)
// ---------------------------------------------------------------------------
#define BMH 128
#define BNH 128
#define BKH 8

__global__ __launch_bounds__(256) void sgemm_kernel(
    const float* __restrict__ A, const float* __restrict__ B,
    const float* __restrict__ bias, float* __restrict__ C, int M, int N, int K)
{
    __shared__ float As[BKH][BMH];
    __shared__ float Bs[BKH][BNH];
    int row0 = blockIdx.y * BMH;
    int col0 = blockIdx.x * BNH;
    int tid = threadIdx.x;
    int aRow = tid >> 1;
    int aCol = (tid & 1) * 4;
    int bRow = tid >> 5;
    int bCol = (tid & 31) * 4;
    int tx = tid & 15;
    int ty = tid >> 4;
    float acc[8][8];
#pragma unroll
    for (int i = 0; i < 8; i++)
#pragma unroll
        for (int j = 0; j < 8; j++) acc[i][j] = 0.f;
    int nK = K / BKH;
    for (int kt = 0; kt < nK; ++kt) {
        int k0 = kt * BKH;
        float4 av = make_float4(0.f, 0.f, 0.f, 0.f);
        int gr = row0 + aRow;
        if (gr < M) av = *(const float4*)&A[(long long)gr * K + k0 + aCol];
        As[aCol + 0][aRow] = av.x;
        As[aCol + 1][aRow] = av.y;
        As[aCol + 2][aRow] = av.z;
        As[aCol + 3][aRow] = av.w;
        float4 bv = make_float4(0.f, 0.f, 0.f, 0.f);
        int gc = col0 + bCol;
        if (gc < N) bv = *(const float4*)&B[(long long)(k0 + bRow) * N + gc];
        *(float4*)&Bs[bRow][bCol] = bv;
        __syncthreads();
#pragma unroll
        for (int k = 0; k < BKH; k++) {
            float ar[8], br[8];
#pragma unroll
            for (int i = 0; i < 8; i++) ar[i] = As[k][ty * 8 + i];
#pragma unroll
            for (int j = 0; j < 8; j++) br[j] = Bs[k][tx * 8 + j];
#pragma unroll
            for (int i = 0; i < 8; i++)
#pragma unroll
                for (int j = 0; j < 8; j++) acc[i][j] += ar[i] * br[j];
        }
        __syncthreads();
    }
#pragma unroll
    for (int i = 0; i < 8; i++) {
        int r = row0 + ty * 8 + i;
        if (r >= M) continue;
#pragma unroll
        for (int j = 0; j < 8; j++) {
            int c = col0 + tx * 8 + j;
            if (c >= N) continue;
            C[(long long)r * N + c] = acc[i][j] + bias[c];
        }
    }
}

// ---------------------------------------------------------------------------
// Host helpers
// ---------------------------------------------------------------------------
static void zero_buf(float* p, long long n_floats) {
    zero_kernel<<<1024, 256>>>((float4*)p, n_floats / 4);
}

static void gemm_cat(const float* A1, const float* A2, int K1, const float* deg,
                     const __half* Bf,
                     const float* bias, float* C, long long CtS, int trans,
                     int M, int K) {
    dim3 grid((M + 63) / 64, 2, 1);
    mgemm_kernel<1><<<grid, 256, GS_M1>>>(A1, A2, K1, deg,
                                          nullptr, nullptr, nullptr, 0,
                                          Bf, bias, nullptr, 0,
                                          C, 0, CtS, trans, M, K);
}

// z-pair scan GEMM: nzp pairs; tfix>0 -> single plane with ts=tfix
static void gemm_scan(const float* hT, const float* lam, const float* Bp, int tfix,
                      const __half* Bf,
                      const float* bias, const float* Dadd, long long DzS,
                      float* C, long long CzS, int M, int K, int nzp) {
    dim3 grid((M + 63) / 64, 2, nzp);
    mgemm_kernel<0><<<grid, 256, GS_M0>>>(nullptr, nullptr, 0, nullptr,
                                          hT, lam, Bp, tfix,
                                          Bf, bias, Dadd, DzS,
                                          C, CzS, 0, 0, M, K);
}

// ---------------------------------------------------------------------------
// Launch
// ---------------------------------------------------------------------------
extern "C" void kernel_launch(void* const* d_in, const int* in_sizes, int n_in,
                              void* d_out, int out_size) {
    const float* xs      = (const float*)d_in[0];
    const void*  ei      = d_in[1];
    const float* w_pre   = (const float*)d_in[2];
    const float* b_pre   = (const float*)d_in[3];

    const float* w_res0  = (const float*)d_in[4];
    const float* b_res0  = (const float*)d_in[5];
    const float* w_self0 = (const float*)d_in[6];
    const float* w_neigh0= (const float*)d_in[7];
    const float* b_sage0 = (const float*)d_in[8];
    const float* a_log0  = (const float*)d_in[9];
    const float* B0      = (const float*)d_in[10];
    const float* w_mix0  = (const float*)d_in[11];
    const float* b_mix0  = (const float*)d_in[12];

    const float* w_res1  = (const float*)d_in[13];
    const float* b_res1  = (const float*)d_in[14];
    const float* w_self1 = (const float*)d_in[15];
    const float* w_neigh1= (const float*)d_in[16];
    const float* b_sage1 = (const float*)d_in[17];
    const float* a_log1  = (const float*)d_in[18];
    const float* B1      = (const float*)d_in[19];
    const float* w_mix1  = (const float*)d_in[20];
    const float* b_mix1  = (const float*)d_in[21];

    const float* w_out   = (const float*)d_in[22];
    const float* b_out   = (const float*)d_in[23];

    float *x0, *x1, *hT, *xsr, *agg, *deg, *lam, *xlast, *xsrl;
    cudaGetSymbolAddress((void**)&x0,    g_x0);
    cudaGetSymbolAddress((void**)&x1,    g_x1);
    cudaGetSymbolAddress((void**)&hT,    g_hT);
    cudaGetSymbolAddress((void**)&xsr,   g_xsr);
    cudaGetSymbolAddress((void**)&agg,   g_agg);
    cudaGetSymbolAddress((void**)&deg,   g_deg);
    cudaGetSymbolAddress((void**)&lam,   g_lam);
    cudaGetSymbolAddress((void**)&xlast, g_xlast);
    cudaGetSymbolAddress((void**)&xsrl,  g_xsrl);

    __half *cat0f, *cat1f, *res0f, *res1f, *mix0f, *mix1f;
    cudaGetSymbolAddress((void**)&cat0f, g_cat0_f);
    cudaGetSymbolAddress((void**)&cat1f, g_cat1_f);
    cudaGetSymbolAddress((void**)&res0f, g_res0_f);
    cudaGetSymbolAddress((void**)&res1f, g_res1_f);
    cudaGetSymbolAddress((void**)&mix0f, g_mix0_f);
    cudaGetSymbolAddress((void**)&mix1f, g_mix1_f);

    cudaFuncSetAttribute(mgemm_kernel<0>,
                         cudaFuncAttributeMaxDynamicSharedMemorySize, GS_M0);
    cudaFuncSetAttribute(mgemm_kernel<1>,
                         cudaFuncAttributeMaxDynamicSharedMemorySize, GS_M1);

    auto fw = [](const float* w1, const float* w2, int K1, int Kt, __half* out) {
        long long tot = (long long)Kt * 256;
        f16w_kernel<<<(int)((tot + 255) / 256), 256>>>(w1, w2, K1, Kt, out);
    };

    detect_kernel<<<1, 32>>>((const unsigned int*)ei);
    lam_kernel<<<(2 * HD + 255) / 256, 256>>>(a_log0, a_log1, lam);
    token_mix_kernel<<<(TV * C_IN + 255) / 256, 256>>>(xs, w_pre, b_pre, x0);
    fw(w_self0, w_neigh0, C_IN, 2 * C_IN, cat0f);
    zero_buf(agg, (long long)TV * C_IN);
    zero_buf(deg, (long long)TV);
    {
        long long tot = (long long)T * E * (C_IN / 4);
        scatter_kernel<<<(int)((tot + 255) / 256), 256>>>(x0, ei, agg, deg, C_IN);
    }
    fw(w_self1, w_neigh1, H, 2 * H, cat1f);
    fw(w_res0, nullptr, C_IN, C_IN, res0f);
    fw(w_res1, nullptr, H, H, res1f);
    fw(w_mix0, nullptr, HD, HD, mix0f);
    fw(w_mix1, nullptr, HD, HD, mix1f);

    // ---------------- layer 0 ----------------
    gemm_cat(x0, agg, C_IN, deg, cat0f, b_sage0, hT, TV, 1, TV, 2 * C_IN);
    gemm_cat(x0, x0,  C_IN, nullptr, res0f, b_res0, xsr, 0, 0, TV, C_IN);

    // mix0: 4 z-pair launches cover t=0..7 (plane0 ts=2z+1, plane1 ts=2z+2)
    gemm_scan(hT, lam, B0, 0, mix0f, b_mix0,
              xsr, (long long)V * H, x1, (long long)V * H, V, HD, 4);

    // ---------------- layer 1 ----------------
    zero_buf(agg, (long long)TV * H);
    {
        long long tot = (long long)T * E * (H / 4);
        scatter_kernel<<<(int)((tot + 255) / 256), 256>>>(x1, ei, agg, nullptr, H);
    }
    gemm_cat(x1, agg, H, deg, cat1f, b_sage1, hT, TV, 1, TV, 2 * H);
    gemm_cat(x1 + (long long)(T - 1) * V * H, x1 + (long long)(T - 1) * V * H, H,
             nullptr, res1f, b_res1, xsrl, 0, 0, V, H);

    // mix1: full 8-step scan, single plane
    gemm_scan(hT, lam + HD, B1, T, mix1f, b_mix1,
              xsrl, 0, xlast, 0, V, HD, 1);

    // ---------------- output head ----------------
    dim3 og((C_OUT + BNH - 1) / BNH, (V + BMH - 1) / BMH);
    sgemm_kernel<<<og, 256>>>(xlast, w_out, b_out, (float*)d_out, V, C_OUT, H);
}

// round 13
// speedup vs baseline: 2.7724x; 2.7724x over previous
#include <cuda_runtime.h>
#include <cuda_bf16.h>
#include <cuda_fp16.h>
#include <cstdint>

#define T 8
#define V 10000
#define E 100000
#define C_IN 128
#define H 256
#define DS 16
#define C_OUT 64
#define HD (H * DS)          // 4096
#define TV (T * V)           // 80000

// ---------------------------------------------------------------------------
// Scratch (device globals; no allocation allowed)
// ---------------------------------------------------------------------------
__device__ __align__(128) float g_x0[(size_t)TV * C_IN];
__device__ __align__(128) float g_x1[(size_t)TV * H];
__device__ __align__(128) float g_hT[(size_t)H * TV];   // sage output, [hh][t][v]
__device__ __align__(128) float g_xsr[(size_t)TV * H];
__device__ __align__(128) float g_agg[(size_t)TV * H];
__device__ __align__(128) float g_deg[(size_t)TV];
__device__ __align__(128) float g_lam[2 * HD];
__device__ __align__(128) float g_xlast[(size_t)V * H];
__device__ __align__(128) float g_xsrl [(size_t)V * H];
__device__ int g_is64;

// fp16 single-plane transposed weights ([N=256][K], K-major)
__device__ __align__(128) __half g_cat0_f[256 * 256];
__device__ __align__(128) __half g_cat1_f[256 * 512];
__device__ __align__(128) __half g_res0_f[256 * 128];
__device__ __align__(128) __half g_res1_f[256 * 256];
__device__ __align__(128) __half g_mix0_f[256 * HD];
__device__ __align__(128) __half g_mix1_f[256 * HD];

// ---------------------------------------------------------------------------
// Helpers
// ---------------------------------------------------------------------------
__device__ __forceinline__ uint32_t smem_u32(const void* p) {
    uint32_t a;
    asm("{ .reg .u64 t; cvta.to.shared.u64 t, %1; cvt.u32.u64 %0, t; }" : "=r"(a) : "l"(p));
    return a;
}

__device__ __forceinline__ uint32_t pack2h(float a, float b) {
    __half h0 = __float2half_rn(a);
    __half h1 = __float2half_rn(b);
    return (uint32_t)__half_as_ushort(h0) | ((uint32_t)__half_as_ushort(h1) << 16);
}

#define LDSM_X4(r0, r1, r2, r3, addr) \
    asm volatile("ldmatrix.sync.aligned.m8n8.x4.shared.b16 {%0,%1,%2,%3}, [%4];" \
        : "=r"(r0), "=r"(r1), "=r"(r2), "=r"(r3) : "r"(addr))

#define MMA_F16(d, a, b0, b1) \
    asm volatile("mma.sync.aligned.m16n8k16.row.col.f32.f16.f16.f32 " \
        "{%0,%1,%2,%3}, {%4,%5,%6,%7}, {%8,%9}, {%0,%1,%2,%3};" \
        : "+f"((d)[0]), "+f"((d)[1]), "+f"((d)[2]), "+f"((d)[3]) \
        : "r"((a)[0]), "r"((a)[1]), "r"((a)[2]), "r"((a)[3]), "r"(b0), "r"(b1))

#define CP16(dst, src) \
    asm volatile("cp.async.cg.shared.global [%0], [%1], 16;" :: "r"(dst), "l"(src))
#define CP_COMMIT() asm volatile("cp.async.commit_group;" ::: "memory")
#define CP_WAIT0()  asm volatile("cp.async.wait_group 0;" ::: "memory")

// ---------------------------------------------------------------------------
// Small kernels
// ---------------------------------------------------------------------------
__global__ void zero_kernel(float4* p, long long n4) {
    long long i = blockIdx.x * (long long)blockDim.x + threadIdx.x;
    long long stride = (long long)gridDim.x * blockDim.x;
    for (; i < n4; i += stride) p[i] = make_float4(0.f, 0.f, 0.f, 0.f);
}

__global__ void detect_kernel(const unsigned int* ei) {
    if (threadIdx.x == 0 && blockIdx.x == 0) {
        unsigned int s = 0;
        for (int i = 0; i < 64; i++) s |= ei[2 * i + 1];
        g_is64 = (s == 0) ? 1 : 0;
    }
}

__device__ __forceinline__ int load_edge(const void* ei, long long pos) {
    if (g_is64) return (int)((const long long*)ei)[pos];
    return ((const int*)ei)[pos];
}

__global__ void lam_kernel(const float* a0, const float* a1, float* lam) {
    int i = blockIdx.x * blockDim.x + threadIdx.x;
    if (i < HD)           lam[i] = expf(-expf(a0[i]));
    else if (i < 2 * HD)  lam[i] = expf(-expf(a1[i - HD]));
}

__global__ void token_mix_kernel(const float* __restrict__ xs,
                                 const float* __restrict__ w,
                                 const float* __restrict__ b,
                                 float* __restrict__ out) {
    int idx = blockIdx.x * blockDim.x + threadIdx.x;
    if (idx >= TV * C_IN) return;
    int c = idx % C_IN;
    int t = idx / (V * C_IN);
    float acc = b[c] + xs[idx] * w[c * 3 + 1];
    if (t > 0)     acc += xs[idx - V * C_IN] * w[c * 3 + 0];
    if (t < T - 1) acc += xs[idx + V * C_IN] * w[c * 3 + 2];
    out[idx] = acc;
}

// scatter with fused degree accumulation (c4 == 0 lane adds 1 to deg)
__global__ void scatter_kernel(const float* __restrict__ x, const void* __restrict__ ei,
                               float* __restrict__ agg, float* __restrict__ deg, int C) {
    int chunks = C >> 2;
    long long idx = blockIdx.x * (long long)blockDim.x + threadIdx.x;
    long long total = (long long)T * E * chunks;
    if (idx >= total) return;
    int c4 = (int)(idx % chunks);
    long long te = idx / chunks;
    int e = (int)(te % E);
    int t = (int)(te / E);
    long long base = (long long)t * 2 * E;
    int src = load_edge(ei, base + e);
    int dst = load_edge(ei, base + E + e);
    float4 v = *(const float4*)&x[((long long)t * V + src) * C + c4 * 4];
    float* p = &agg[((long long)t * V + dst) * C + c4 * 4];
    asm volatile("red.global.add.v4.f32 [%0], {%1,%2,%3,%4};"
                 :: "l"(p), "f"(v.x), "f"(v.y), "f"(v.z), "f"(v.w) : "memory");
    if (deg && c4 == 0) {
        float* dp = &deg[(long long)t * V + dst];
        asm volatile("red.global.add.f32 [%0], %1;" :: "l"(dp), "f"(1.0f) : "memory");
    }
}

// Build transposed fp16 weights: dst[n][k] = rn(concat(w1,w2)[k][n])
__global__ void f16w_kernel(const float* __restrict__ w1, const float* __restrict__ w2,
                            int K1, int Kt, __half* __restrict__ out) {
    long long idx = blockIdx.x * (long long)blockDim.x + threadIdx.x;
    if (idx >= (long long)Kt * 256) return;
    int k = (int)(idx % Kt);
    int n = (int)(idx / Kt);
    float v = (k < K1) ? w1[(long long)k * 256 + n] : w2[(long long)(k - K1) * 256 + n];
    out[(long long)n * Kt + k] = __float2half_rn(v);
}

// ---------------------------------------------------------------------------
// fp16 1-product tensor GEMM, tile 64x128, BK=64, 256 threads (8 warps
// 2m x 4n, warp tile 32x32), 2 CTAs/SM, double-buffered SMEM, cp.async B.
//   MODE 0 (scan-fused): A[r,k] = rn16(relu(Horner to ts)); lam/Bp preloaded
//       into SMEM once; each thread owns one hh column (16 k).
//   MODE 1 (cat): A[r,k] = rn16(concat(A1, A2*invdeg)[r,k]).
// C[M, n0..n0+127] = A @ B^T + bias (+ Dadd); optional transposed output.
// ---------------------------------------------------------------------------
#define ROWB 144                      // 64 k * 2B + 16 pad
#define AH_T 9216                     // 64 * 144
#define BH_T 18432                    // 128 * 144
#define STG  (AH_T + BH_T)            // 27648
#define LAM_OFF (2 * STG)             // 55296
#define GS_M0 (2 * STG + 32768)       // 88064 (lam 16K + Bp 16K)
#define GS_M1 (2 * STG)               // 55296

template <int MODE>
__global__ __launch_bounds__(256, 2) void mgemm_kernel(
    const float* __restrict__ A1, const float* __restrict__ A2, int K1,
    const float* __restrict__ deg,
    const float* __restrict__ hT, const float* __restrict__ lam,
    const float* __restrict__ Bp, int tfix,
    const __half* __restrict__ Bf,
    const float* __restrict__ bias,
    const float* __restrict__ Dadd, long long DzS,
    float* __restrict__ Cout, long long CzS, long long CtS, int trans_out,
    int M, int K)
{
    extern __shared__ char smem[];
    const uint32_t sb = smem_u32(smem);
    const int tid = threadIdx.x;
    const int wid = tid >> 5;
    const int lane = tid & 31;
    const int warp_m = wid >> 2;       // 0..1
    const int warp_n = wid & 3;        // 0..3
    const int z = blockIdx.z;
    const long long m0 = (long long)blockIdx.x * 64;
    const int n0 = blockIdx.y * 128;

    const float* Dz = Dadd ? (Dadd + (long long)z * DzS) : (const float*)0;
    float* Cz = Cout + (long long)z * CzS;

    float acc[2][4][4];
#pragma unroll
    for (int i = 0; i < 2; i++)
#pragma unroll
        for (int j = 0; j < 4; j++)
#pragma unroll
            for (int p = 0; p < 4; p++) acc[i][j][p] = 0.f;

    const int nK = K / 64;
    const int ts = (MODE == 0) ? (tfix > 0 ? tfix : z + 1) : 0;

    // producer coords: q = 16-k segment (0..3), r = row (0..63)
    const int q = tid >> 6;
    const int r = tid & 63;
    const long long rg1 = m0 + r;
    const bool rowok = (rg1 < M);

    float a16[16];                     // MODE 1 staging
    float hx[8];                       // MODE 0 staging (one hh column)

    const uint32_t aoff = (uint32_t)(warp_m * 32 + (lane & 15)) * ROWB +
                          (uint32_t)((lane >> 4) << 3) * 2;
    const uint32_t boff = (uint32_t)(warp_n * 32 + ((lane >> 4) << 3) + (lane & 7)) * ROWB +
                          (uint32_t)(((lane >> 3) & 1) << 3) * 2;

    if (MODE == 0) {
#pragma unroll
        for (int j = 0; j < 4; j++) {
            int idx = tid + 256 * j;
            *(float4*)(smem + LAM_OFF + idx * 16)         = ((const float4*)lam)[idx];
            *(float4*)(smem + LAM_OFF + 16384 + idx * 16) = ((const float4*)Bp)[idx];
        }
    }

    auto cpB = [&](int kt, int stage) {
        const int k0 = kt * 64;
        const uint32_t base = sb + stage * STG + AH_T;
#pragma unroll
        for (int i = 0; i < 4; i++) {
            int idx = tid + 256 * i;
            int n  = idx >> 3;
            int kq = idx & 7;
            uint32_t dst = base + (uint32_t)n * ROWB + (uint32_t)kq * 16;
            long long soff = (long long)(n0 + n) * K + k0 + kq * 8;
            CP16(dst, Bf + soff);
        }
    };

    auto prefA = [&](int kt) {
        const int kg = kt * 64 + q * 16;
        if (MODE == 0) {
            const int hh = kg >> 4;
            const long long hb = (long long)hh * TV + rg1;
#pragma unroll
            for (int tt = 0; tt < 8; tt++)
                hx[tt] = (rowok && tt < ts) ? hT[hb + (long long)tt * V] : 0.f;
        } else {
            if (rowok) {
                bool second = (kg >= K1);
                const float* src = second ? &A2[rg1 * (long long)(K - K1) + (kg - K1)]
                                          : &A1[rg1 * (long long)K1 + kg];
#pragma unroll
                for (int f = 0; f < 4; f++)
                    *(float4*)&a16[f * 4] = ((const float4*)src)[f];
                if (second && deg) {
                    float inv = 1.0f / fmaxf(deg[rg1], 1.0f);
#pragma unroll
                    for (int d = 0; d < 16; d++) a16[d] *= inv;
                }
            } else {
#pragma unroll
                for (int d = 0; d < 16; d++) a16[d] = 0.f;
            }
        }
    };

    auto produceA = [&](int stage, int kt) {
        const uint32_t off = (uint32_t)stage * STG + (uint32_t)r * ROWB + (uint32_t)q * 32;
        if (MODE == 0) {
            const int kg = kt * 64 + q * 16;
            float lam16[16], b16[16];
#pragma unroll
            for (int f = 0; f < 4; f++) {
                *(float4*)&lam16[f * 4] = *(const float4*)(smem + LAM_OFF + kg * 4 + f * 16);
                *(float4*)&b16[f * 4]   = *(const float4*)(smem + LAM_OFF + 16384 + kg * 4 + f * 16);
            }
            float s[16];
#pragma unroll
            for (int d = 0; d < 16; d++) s[d] = 0.f;
#pragma unroll
            for (int tt = 0; tt < 8; tt++) {
                if (tt < ts) {
                    float x = hx[tt];
#pragma unroll
                    for (int d = 0; d < 16; d++) s[d] = lam16[d] * s[d] + x * b16[d];
                }
            }
            uint32_t u[8];
#pragma unroll
            for (int d2 = 0; d2 < 8; d2++)
                u[d2] = pack2h(fmaxf(s[d2 * 2], 0.f), fmaxf(s[d2 * 2 + 1], 0.f));
            *(uint4*)(smem + off)      = make_uint4(u[0], u[1], u[2], u[3]);
            *(uint4*)(smem + off + 16) = make_uint4(u[4], u[5], u[6], u[7]);
        } else {
            uint32_t u[8];
#pragma unroll
            for (int d2 = 0; d2 < 8; d2++)
                u[d2] = pack2h(a16[d2 * 2], a16[d2 * 2 + 1]);
            *(uint4*)(smem + off)      = make_uint4(u[0], u[1], u[2], u[3]);
            *(uint4*)(smem + off + 16) = make_uint4(u[4], u[5], u[6], u[7]);
        }
    };

    auto compute = [&](int stage) {
        const uint32_t base = sb + stage * STG;
#pragma unroll
        for (int ks = 0; ks < 4; ks++) {
            const uint32_t kk = (uint32_t)ks * 32;
            uint32_t a_h[2][4];
#pragma unroll
            for (int i = 0; i < 2; i++) {
                uint32_t ad = base + aoff + (uint32_t)(i * 16) * ROWB + kk;
                LDSM_X4(a_h[i][0], a_h[i][1], a_h[i][2], a_h[i][3], ad);
            }
            uint32_t b_h[8];
#pragma unroll
            for (int jj = 0; jj < 2; jj++) {
                uint32_t bd = base + AH_T + boff + (uint32_t)(jj * 16) * ROWB + kk;
                LDSM_X4(b_h[jj * 4 + 0], b_h[jj * 4 + 1], b_h[jj * 4 + 2], b_h[jj * 4 + 3], bd);
            }
#pragma unroll
            for (int i = 0; i < 2; i++)
#pragma unroll
                for (int j = 0; j < 4; j++)
                    MMA_F16(acc[i][j], a_h[i], b_h[j * 2], b_h[j * 2 + 1]);
        }
    };

    // prologue
    prefA(0);
    cpB(0, 0);
    CP_COMMIT();
    if (MODE == 0) __syncthreads();    // lam/Bp smem visible
    produceA(0, 0);
    CP_WAIT0();
    __syncthreads();

    for (int kt = 0; kt < nK; kt++) {
        const int cur = kt & 1;
        const bool more = (kt + 1 < nK);
        if (more) {
            prefA(kt + 1);
            cpB(kt + 1, cur ^ 1);
            CP_COMMIT();
        }
        compute(cur);
        if (more) produceA(cur ^ 1, kt + 1);
        CP_WAIT0();
        __syncthreads();
    }

    // epilogue: warp tile 32x32 at (warp_m*32, warp_n*32)
#pragma unroll
    for (int i = 0; i < 2; i++) {
        long long r1 = m0 + warp_m * 32 + i * 16 + (lane >> 2);
        long long r2 = r1 + 8;
#pragma unroll
        for (int j = 0; j < 4; j++) {
            int c = n0 + warp_n * 32 + j * 8 + (lane & 3) * 2;
            float bx = 0.f, by = 0.f;
            if (bias) { float2 b2 = *(const float2*)&bias[c]; bx = b2.x; by = b2.y; }
            if (r1 < M) {
                float vx = acc[i][j][0] + bx, vy = acc[i][j][1] + by;
                if (Dz) { float2 d = *(const float2*)&Dz[r1 * 256 + c]; vx += d.x; vy += d.y; }
                if (trans_out) {
                    Cz[(long long)c * CtS + r1]       = vx;
                    Cz[(long long)(c + 1) * CtS + r1] = vy;
                } else {
                    *(float2*)&Cz[r1 * 256 + c] = make_float2(vx, vy);
                }
            }
            if (r2 < M) {
                float vx = acc[i][j][2] + bx, vy = acc[i][j][3] + by;
                if (Dz) { float2 d = *(const float2*)&Dz[r2 * 256 + c]; vx += d.x; vy += d.y; }
                if (trans_out) {
                    Cz[(long long)c * CtS + r2]       = vx;
                    Cz[(long long)(c + 1) * CtS + r2] = vy;
                } else {
                    *(float2*)&Cz[r2 * 256 + c] = make_float2(vx, vy);
                }
            }
        }
    }
}

// ---------------------------------------------------------------------------
// fp32 SGEMM for the small output head (N=64)
// ---------------------------------------------------------------------------
#define BMH 128
#define BNH 128
#define BKH 8

__global__ __launch_bounds__(256) void sgemm_kernel(
    const float* __restrict__ A, const float* __restrict__ B,
    const float* __restrict__ bias, float* __restrict__ C, int M, int N, int K)
{
    __shared__ float As[BKH][BMH];
    __shared__ float Bs[BKH][BNH];
    int row0 = blockIdx.y * BMH;
    int col0 = blockIdx.x * BNH;
    int tid = threadIdx.x;
    int aRow = tid >> 1;
    int aCol = (tid & 1) * 4;
    int bRow = tid >> 5;
    int bCol = (tid & 31) * 4;
    int tx = tid & 15;
    int ty = tid >> 4;
    float acc[8][8];
#pragma unroll
    for (int i = 0; i < 8; i++)
#pragma unroll
        for (int j = 0; j < 8; j++) acc[i][j] = 0.f;
    int nK = K / BKH;
    for (int kt = 0; kt < nK; ++kt) {
        int k0 = kt * BKH;
        float4 av = make_float4(0.f, 0.f, 0.f, 0.f);
        int gr = row0 + aRow;
        if (gr < M) av = *(const float4*)&A[(long long)gr * K + k0 + aCol];
        As[aCol + 0][aRow] = av.x;
        As[aCol + 1][aRow] = av.y;
        As[aCol + 2][aRow] = av.z;
        As[aCol + 3][aRow] = av.w;
        float4 bv = make_float4(0.f, 0.f, 0.f, 0.f);
        int gc = col0 + bCol;
        if (gc < N) bv = *(const float4*)&B[(long long)(k0 + bRow) * N + gc];
        *(float4*)&Bs[bRow][bCol] = bv;
        __syncthreads();
#pragma unroll
        for (int k = 0; k < BKH; k++) {
            float ar[8], br[8];
#pragma unroll
            for (int i = 0; i < 8; i++) ar[i] = As[k][ty * 8 + i];
#pragma unroll
            for (int j = 0; j < 8; j++) br[j] = Bs[k][tx * 8 + j];
#pragma unroll
            for (int i = 0; i < 8; i++)
#pragma unroll
                for (int j = 0; j < 8; j++) acc[i][j] += ar[i] * br[j];
        }
        __syncthreads();
    }
#pragma unroll
    for (int i = 0; i < 8; i++) {
        int r = row0 + ty * 8 + i;
        if (r >= M) continue;
#pragma unroll
        for (int j = 0; j < 8; j++) {
            int c = col0 + tx * 8 + j;
            if (c >= N) continue;
            C[(long long)r * N + c] = acc[i][j] + bias[c];
        }
    }
}

// ---------------------------------------------------------------------------
// Host helpers
// ---------------------------------------------------------------------------
static void zero_buf(float* p, long long n_floats) {
    zero_kernel<<<1024, 256>>>((float4*)p, n_floats / 4);
}

static void gemm_cat(const float* A1, const float* A2, int K1, const float* deg,
                     const __half* Bf,
                     const float* bias, float* C, long long CtS, int trans,
                     int M, int K) {
    dim3 grid((M + 63) / 64, 2, 1);
    mgemm_kernel<1><<<grid, 256, GS_M1>>>(A1, A2, K1, deg,
                                          nullptr, nullptr, nullptr, 0,
                                          Bf, bias, nullptr, 0,
                                          C, 0, CtS, trans, M, K);
}

static void gemm_scan(const float* hT, const float* lam, const float* Bp, int tfix,
                      const __half* Bf,
                      const float* bias, const float* Dadd, long long DzS,
                      float* C, long long CzS, int M, int K, int nz) {
    dim3 grid((M + 63) / 64, 2, nz);
    mgemm_kernel<0><<<grid, 256, GS_M0>>>(nullptr, nullptr, 0, nullptr,
                                          hT, lam, Bp, tfix,
                                          Bf, bias, Dadd, DzS,
                                          C, CzS, 0, 0, M, K);
}

// ---------------------------------------------------------------------------
// Launch
// ---------------------------------------------------------------------------
extern "C" void kernel_launch(void* const* d_in, const int* in_sizes, int n_in,
                              void* d_out, int out_size) {
    const float* xs      = (const float*)d_in[0];
    const void*  ei      = d_in[1];
    const float* w_pre   = (const float*)d_in[2];
    const float* b_pre   = (const float*)d_in[3];

    const float* w_res0  = (const float*)d_in[4];
    const float* b_res0  = (const float*)d_in[5];
    const float* w_self0 = (const float*)d_in[6];
    const float* w_neigh0= (const float*)d_in[7];
    const float* b_sage0 = (const float*)d_in[8];
    const float* a_log0  = (const float*)d_in[9];
    const float* B0      = (const float*)d_in[10];
    const float* w_mix0  = (const float*)d_in[11];
    const float* b_mix0  = (const float*)d_in[12];

    const float* w_res1  = (const float*)d_in[13];
    const float* b_res1  = (const float*)d_in[14];
    const float* w_self1 = (const float*)d_in[15];
    const float* w_neigh1= (const float*)d_in[16];
    const float* b_sage1 = (const float*)d_in[17];
    const float* a_log1  = (const float*)d_in[18];
    const float* B1      = (const float*)d_in[19];
    const float* w_mix1  = (const float*)d_in[20];
    const float* b_mix1  = (const float*)d_in[21];

    const float* w_out   = (const float*)d_in[22];
    const float* b_out   = (const float*)d_in[23];

    float *x0, *x1, *hT, *xsr, *agg, *deg, *lam, *xlast, *xsrl;
    cudaGetSymbolAddress((void**)&x0,    g_x0);
    cudaGetSymbolAddress((void**)&x1,    g_x1);
    cudaGetSymbolAddress((void**)&hT,    g_hT);
    cudaGetSymbolAddress((void**)&xsr,   g_xsr);
    cudaGetSymbolAddress((void**)&agg,   g_agg);
    cudaGetSymbolAddress((void**)&deg,   g_deg);
    cudaGetSymbolAddress((void**)&lam,   g_lam);
    cudaGetSymbolAddress((void**)&xlast, g_xlast);
    cudaGetSymbolAddress((void**)&xsrl,  g_xsrl);

    __half *cat0f, *cat1f, *res0f, *res1f, *mix0f, *mix1f;
    cudaGetSymbolAddress((void**)&cat0f, g_cat0_f);
    cudaGetSymbolAddress((void**)&cat1f, g_cat1_f);
    cudaGetSymbolAddress((void**)&res0f, g_res0_f);
    cudaGetSymbolAddress((void**)&res1f, g_res1_f);
    cudaGetSymbolAddress((void**)&mix0f, g_mix0_f);
    cudaGetSymbolAddress((void**)&mix1f, g_mix1_f);

    cudaFuncSetAttribute(mgemm_kernel<0>,
                         cudaFuncAttributeMaxDynamicSharedMemorySize, GS_M0);
    cudaFuncSetAttribute(mgemm_kernel<1>,
                         cudaFuncAttributeMaxDynamicSharedMemorySize, GS_M1);

    auto fw = [](const float* w1, const float* w2, int K1, int Kt, __half* out) {
        long long tot = (long long)Kt * 256;
        f16w_kernel<<<(int)((tot + 255) / 256), 256>>>(w1, w2, K1, Kt, out);
    };

    // Launch order: 6th launch (ncu -s 5 -c 1) is the layer-0 scatter_kernel.
    detect_kernel<<<1, 32>>>((const unsigned int*)ei);                        // 1
    lam_kernel<<<(2 * HD + 255) / 256, 256>>>(a_log0, a_log1, lam);           // 2
    token_mix_kernel<<<(TV * C_IN + 255) / 256, 256>>>(xs, w_pre, b_pre, x0); // 3
    zero_buf(agg, (long long)TV * C_IN);                                      // 4
    zero_buf(deg, (long long)TV);                                             // 5
    {
        long long tot = (long long)T * E * (C_IN / 4);
        scatter_kernel<<<(int)((tot + 255) / 256), 256>>>(x0, ei, agg, deg, C_IN); // 6
    }
    fw(w_self0, w_neigh0, C_IN, 2 * C_IN, cat0f);
    fw(w_self1, w_neigh1, H, 2 * H, cat1f);
    fw(w_res0, nullptr, C_IN, C_IN, res0f);
    fw(w_res1, nullptr, H, H, res1f);
    fw(w_mix0, nullptr, HD, HD, mix0f);
    fw(w_mix1, nullptr, HD, HD, mix1f);

    // ---------------- layer 0 ----------------
    gemm_cat(x0, agg, C_IN, deg, cat0f, b_sage0, hT, TV, 1, TV, 2 * C_IN);
    gemm_cat(x0, x0,  C_IN, nullptr, res0f, b_res0, xsr, 0, 0, TV, C_IN);

    // all 8 mix0 GEMMs, scan fused in producer (ts = z+1), fp16 1-product
    gemm_scan(hT, lam, B0, 0, mix0f, b_mix0,
              xsr, (long long)V * H, x1, (long long)V * H, V, HD, T);

    // ---------------- layer 1 ----------------
    zero_buf(agg, (long long)TV * H);
    {
        long long tot = (long long)T * E * (H / 4);
        scatter_kernel<<<(int)((tot + 255) / 256), 256>>>(x1, ei, agg, nullptr, H);
    }
    gemm_cat(x1, agg, H, deg, cat1f, b_sage1, hT, TV, 1, TV, 2 * H);
    gemm_cat(x1 + (long long)(T - 1) * V * H, x1 + (long long)(T - 1) * V * H, H,
             nullptr, res1f, b_res1, xsrl, 0, 0, V, H);

    // mix1: full 8-step scan, single plane
    gemm_scan(hT, lam + HD, B1, T, mix1f, b_mix1,
              xsrl, 0, xlast, 0, V, HD, 1);

    // ---------------- output head ----------------
    dim3 og((C_OUT + BNH - 1) / BNH, (V + BMH - 1) / BMH);
    sgemm_kernel<<<og, 256>>>(xlast, w_out, b_out, (float*)d_out, V, C_OUT, H);
}

// round 14
// speedup vs baseline: 2.8058x; 1.0120x over previous
#include <cuda_runtime.h>
#include <cuda_bf16.h>
#include <cuda_fp16.h>
#include <cstdint>

#define T 8
#define V 10000
#define E 100000
#define C_IN 128
#define H 256
#define DS 16
#define C_OUT 64
#define HD (H * DS)          // 4096
#define TV (T * V)           // 80000

// ---------------------------------------------------------------------------
// Scratch (device globals; no allocation allowed)
// ---------------------------------------------------------------------------
__device__ __align__(128) float g_x0[(size_t)TV * C_IN];
__device__ __align__(128) float g_x1[(size_t)TV * H];
__device__ __align__(128) float g_hT[(size_t)H * TV];   // sage output, [hh][t][v]
__device__ __align__(128) float g_xsr[(size_t)TV * H];
__device__ __align__(128) float g_agg[(size_t)TV * H];
__device__ __align__(128) float g_deg[(size_t)TV];
__device__ __align__(128) float g_lam[2 * HD];
__device__ __align__(128) float g_xlast[(size_t)V * H];
__device__ __align__(128) float g_xsrl [(size_t)V * H];
__device__ int g_is64;

// fp16 single-plane transposed weights ([N=256][K], K-major)
__device__ __align__(128) __half g_cat0_f[256 * 256];
__device__ __align__(128) __half g_cat1_f[256 * 512];
__device__ __align__(128) __half g_res0_f[256 * 128];
__device__ __align__(128) __half g_res1_f[256 * 256];
__device__ __align__(128) __half g_mix0_f[256 * HD];
__device__ __align__(128) __half g_mix1_f[256 * HD];

// ---------------------------------------------------------------------------
// Helpers
// ---------------------------------------------------------------------------
__device__ __forceinline__ uint32_t smem_u32(const void* p) {
    uint32_t a;
    asm("{ .reg .u64 t; cvta.to.shared.u64 t, %1; cvt.u32.u64 %0, t; }" : "=r"(a) : "l"(p));
    return a;
}

__device__ __forceinline__ uint32_t pack2h(float a, float b) {
    __half h0 = __float2half_rn(a);
    __half h1 = __float2half_rn(b);
    return (uint32_t)__half_as_ushort(h0) | ((uint32_t)__half_as_ushort(h1) << 16);
}

#define LDSM_X4(r0, r1, r2, r3, addr) \
    asm volatile("ldmatrix.sync.aligned.m8n8.x4.shared.b16 {%0,%1,%2,%3}, [%4];" \
        : "=r"(r0), "=r"(r1), "=r"(r2), "=r"(r3) : "r"(addr))

#define MMA_F16(d, a, b0, b1) \
    asm volatile("mma.sync.aligned.m16n8k16.row.col.f32.f16.f16.f32 " \
        "{%0,%1,%2,%3}, {%4,%5,%6,%7}, {%8,%9}, {%0,%1,%2,%3};" \
        : "+f"((d)[0]), "+f"((d)[1]), "+f"((d)[2]), "+f"((d)[3]) \
        : "r"((a)[0]), "r"((a)[1]), "r"((a)[2]), "r"((a)[3]), "r"(b0), "r"(b1))

#define CP16(dst, src) \
    asm volatile("cp.async.cg.shared.global [%0], [%1], 16;" :: "r"(dst), "l"(src))
#define CP_COMMIT() asm volatile("cp.async.commit_group;" ::: "memory")
#define CP_WAIT0()  asm volatile("cp.async.wait_group 0;" ::: "memory")

// ---------------------------------------------------------------------------
// Small kernels
// ---------------------------------------------------------------------------
__global__ void zero_kernel(float4* p, long long n4) {
    long long i = blockIdx.x * (long long)blockDim.x + threadIdx.x;
    long long stride = (long long)gridDim.x * blockDim.x;
    for (; i < n4; i += stride) p[i] = make_float4(0.f, 0.f, 0.f, 0.f);
}

// zero two buffers in one launch
__global__ void zero2_kernel(float4* p1, long long n1, float4* p2, long long n2) {
    long long i = blockIdx.x * (long long)blockDim.x + threadIdx.x;
    long long stride = (long long)gridDim.x * blockDim.x;
    const float4 zz = make_float4(0.f, 0.f, 0.f, 0.f);
    for (long long j = i; j < n1; j += stride) p1[j] = zz;
    for (long long j = i; j < n2; j += stride) p2[j] = zz;
}

__global__ void detect_kernel(const unsigned int* ei) {
    if (threadIdx.x == 0 && blockIdx.x == 0) {
        unsigned int s = 0;
        for (int i = 0; i < 64; i++) s |= ei[2 * i + 1];
        g_is64 = (s == 0) ? 1 : 0;
    }
}

__device__ __forceinline__ int load_edge(const void* ei, long long pos) {
    if (g_is64) return (int)((const long long*)ei)[pos];
    return ((const int*)ei)[pos];
}

__global__ void lam_kernel(const float* a0, const float* a1, float* lam) {
    int i = blockIdx.x * blockDim.x + threadIdx.x;
    if (i < HD)           lam[i] = expf(-expf(a0[i]));
    else if (i < 2 * HD)  lam[i] = expf(-expf(a1[i - HD]));
}

__global__ void token_mix_kernel(const float* __restrict__ xs,
                                 const float* __restrict__ w,
                                 const float* __restrict__ b,
                                 float* __restrict__ out) {
    int idx = blockIdx.x * blockDim.x + threadIdx.x;
    if (idx >= TV * C_IN) return;
    int c = idx % C_IN;
    int t = idx / (V * C_IN);
    float acc = b[c] + xs[idx] * w[c * 3 + 1];
    if (t > 0)     acc += xs[idx - V * C_IN] * w[c * 3 + 0];
    if (t < T - 1) acc += xs[idx + V * C_IN] * w[c * 3 + 2];
    out[idx] = acc;
}

// scatter with fused degree accumulation (c4 == 0 lane adds 1 to deg)
__global__ void scatter_kernel(const float* __restrict__ x, const void* __restrict__ ei,
                               float* __restrict__ agg, float* __restrict__ deg, int C) {
    int chunks = C >> 2;
    long long idx = blockIdx.x * (long long)blockDim.x + threadIdx.x;
    long long total = (long long)T * E * chunks;
    if (idx >= total) return;
    int c4 = (int)(idx % chunks);
    long long te = idx / chunks;
    int e = (int)(te % E);
    int t = (int)(te / E);
    long long base = (long long)t * 2 * E;
    int src = load_edge(ei, base + e);
    int dst = load_edge(ei, base + E + e);
    float4 v = *(const float4*)&x[((long long)t * V + src) * C + c4 * 4];
    float* p = &agg[((long long)t * V + dst) * C + c4 * 4];
    asm volatile("red.global.add.v4.f32 [%0], {%1,%2,%3,%4};"
                 :: "l"(p), "f"(v.x), "f"(v.y), "f"(v.z), "f"(v.w) : "memory");
    if (deg && c4 == 0) {
        float* dp = &deg[(long long)t * V + dst];
        asm volatile("red.global.add.f32 [%0], %1;" :: "l"(dp), "f"(1.0f) : "memory");
    }
}

// Build transposed fp16 weights: dst[n][k] = rn(concat(w1,w2)[k][n])
__global__ void f16w_kernel(const float* __restrict__ w1, const float* __restrict__ w2,
                            int K1, int Kt, __half* __restrict__ out) {
    long long idx = blockIdx.x * (long long)blockDim.x + threadIdx.x;
    if (idx >= (long long)Kt * 256) return;
    int k = (int)(idx % Kt);
    int n = (int)(idx / Kt);
    float v = (k < K1) ? w1[(long long)k * 256 + n] : w2[(long long)(k - K1) * 256 + n];
    out[(long long)n * Kt + k] = __float2half_rn(v);
}

// ---------------------------------------------------------------------------
// Shared GEMM geometry constants
// ---------------------------------------------------------------------------
#define ROWB 144                      // 64 k * 2B + 16 pad

// ---------------------------------------------------------------------------
// MIX kernel (scan-fused, fp16 1-product): tile 64x256 (FULL N, grid_y=1),
// BK=64, 512 threads (16 warps 2m x 8n, warp tile 32x32), 1 CTA/SM.
// A produced ONCE per (m-tile, z) by threads 0..255 (one hh column each);
// lam/Bp preloaded to SMEM; B streamed by all 512 threads via cp.async.
// C[z][M,256] = rn16(relu(scan_ts)) @ Bf^T + bias + Dadd[z]
// ---------------------------------------------------------------------------
#define A_T0 9216                     // 64 * 144
#define B_T0 36864                    // 256 * 144
#define STG0 (A_T0 + B_T0)            // 46080
#define LAM0 (2 * STG0)               // 92160
#define GS0  (LAM0 + 32768)           // 124928

__global__ __launch_bounds__(512, 1) void mix_kernel(
    const float* __restrict__ hT, const float* __restrict__ lam,
    const float* __restrict__ Bp, int tfix,
    const __half* __restrict__ Bf,
    const float* __restrict__ bias,
    const float* __restrict__ Dadd, long long DzS,
    float* __restrict__ Cout, long long CzS,
    int M, int K)
{
    extern __shared__ char smem[];
    const uint32_t sb = smem_u32(smem);
    const int tid = threadIdx.x;
    const int wid = tid >> 5;
    const int lane = tid & 31;
    const int warp_m = wid >> 3;       // 0..1
    const int warp_n = wid & 7;        // 0..7
    const int z = blockIdx.z;
    const long long m0 = (long long)blockIdx.x * 64;

    const float* Dz = Dadd + (long long)z * DzS;
    float* Cz = Cout + (long long)z * CzS;

    float acc[2][4][4];
#pragma unroll
    for (int i = 0; i < 2; i++)
#pragma unroll
        for (int j = 0; j < 4; j++)
#pragma unroll
            for (int p = 0; p < 4; p++) acc[i][j][p] = 0.f;

    const int nK = K / 64;
    const int ts = (tfix > 0) ? tfix : z + 1;

    // producer coords (tid < 256): q = 16-k segment (0..3), r = row (0..63)
    const int q = (tid & 255) >> 6;
    const int r = tid & 63;
    const long long rg1 = m0 + r;
    const bool produce = (tid < 256);
    const bool rowok = (rg1 < M);

    float hx[8];

    const uint32_t aoff = (uint32_t)(warp_m * 32 + (lane & 15)) * ROWB +
                          (uint32_t)((lane >> 4) << 3) * 2;
    const uint32_t boff = (uint32_t)(warp_n * 32 + ((lane >> 4) << 3) + (lane & 7)) * ROWB +
                          (uint32_t)(((lane >> 3) & 1) << 3) * 2;

    // preload lam/Bp into SMEM: 1024 float4 each
#pragma unroll
    for (int j = 0; j < 2; j++) {
        int idx = tid + 512 * j;       // 0..1023
        *(float4*)(smem + LAM0 + idx * 16)         = ((const float4*)lam)[idx];
        *(float4*)(smem + LAM0 + 16384 + idx * 16) = ((const float4*)Bp)[idx];
    }

    auto cpB = [&](int kt, int stage) {
        const int k0 = kt * 64;
        const uint32_t base = sb + stage * STG0 + A_T0;
#pragma unroll
        for (int i = 0; i < 4; i++) {
            int idx = tid + 512 * i;   // 0..2047
            int n  = idx >> 3;         // 0..255
            int kq = idx & 7;
            uint32_t dst = base + (uint32_t)n * ROWB + (uint32_t)kq * 16;
            long long soff = (long long)n * K + k0 + kq * 8;
            CP16(dst, Bf + soff);
        }
    };

    auto prefA = [&](int kt) {
        if (!produce) return;
        const int hh = (kt * 64 + q * 16) >> 4;
        const long long hb = (long long)hh * TV + rg1;
#pragma unroll
        for (int tt = 0; tt < 8; tt++)
            hx[tt] = (rowok && tt < ts) ? hT[hb + (long long)tt * V] : 0.f;
    };

    auto produceA = [&](int stage, int kt) {
        if (!produce) return;
        const uint32_t off = (uint32_t)stage * STG0 + (uint32_t)r * ROWB + (uint32_t)q * 32;
        const int kg = kt * 64 + q * 16;
        float lam16[16], b16[16];
#pragma unroll
        for (int f = 0; f < 4; f++) {
            *(float4*)&lam16[f * 4] = *(const float4*)(smem + LAM0 + kg * 4 + f * 16);
            *(float4*)&b16[f * 4]   = *(const float4*)(smem + LAM0 + 16384 + kg * 4 + f * 16);
        }
        float s[16];
#pragma unroll
        for (int d = 0; d < 16; d++) s[d] = 0.f;
#pragma unroll
        for (int tt = 0; tt < 8; tt++) {
            if (tt < ts) {
                float x = hx[tt];
#pragma unroll
                for (int d = 0; d < 16; d++) s[d] = lam16[d] * s[d] + x * b16[d];
            }
        }
        uint32_t u[8];
#pragma unroll
        for (int d2 = 0; d2 < 8; d2++)
            u[d2] = pack2h(fmaxf(s[d2 * 2], 0.f), fmaxf(s[d2 * 2 + 1], 0.f));
        *(uint4*)(smem + off)      = make_uint4(u[0], u[1], u[2], u[3]);
        *(uint4*)(smem + off + 16) = make_uint4(u[4], u[5], u[6], u[7]);
    };

    auto compute = [&](int stage) {
        const uint32_t base = sb + stage * STG0;
#pragma unroll
        for (int ks = 0; ks < 4; ks++) {
            const uint32_t kk = (uint32_t)ks * 32;
            uint32_t a_h[2][4];
#pragma unroll
            for (int i = 0; i < 2; i++) {
                uint32_t ad = base + aoff + (uint32_t)(i * 16) * ROWB + kk;
                LDSM_X4(a_h[i][0], a_h[i][1], a_h[i][2], a_h[i][3], ad);
            }
            uint32_t b_h[8];
#pragma unroll
            for (int jj = 0; jj < 2; jj++) {
                uint32_t bd = base + A_T0 + boff + (uint32_t)(jj * 16) * ROWB + kk;
                LDSM_X4(b_h[jj * 4 + 0], b_h[jj * 4 + 1], b_h[jj * 4 + 2], b_h[jj * 4 + 3], bd);
            }
#pragma unroll
            for (int i = 0; i < 2; i++)
#pragma unroll
                for (int j = 0; j < 4; j++)
                    MMA_F16(acc[i][j], a_h[i], b_h[j * 2], b_h[j * 2 + 1]);
        }
    };

    // prologue
    prefA(0);
    cpB(0, 0);
    CP_COMMIT();
    __syncthreads();                   // lam/Bp smem visible
    produceA(0, 0);
    CP_WAIT0();
    __syncthreads();

    for (int kt = 0; kt < nK; kt++) {
        const int cur = kt & 1;
        const bool more = (kt + 1 < nK);
        if (more) {
            prefA(kt + 1);
            cpB(kt + 1, cur ^ 1);
            CP_COMMIT();
        }
        compute(cur);
        if (more) produceA(cur ^ 1, kt + 1);
        CP_WAIT0();
        __syncthreads();
    }

    // epilogue: warp tile 32x32 at (warp_m*32, warp_n*32)
#pragma unroll
    for (int i = 0; i < 2; i++) {
        long long r1 = m0 + warp_m * 32 + i * 16 + (lane >> 2);
        long long r2 = r1 + 8;
#pragma unroll
        for (int j = 0; j < 4; j++) {
            int c = warp_n * 32 + j * 8 + (lane & 3) * 2;
            float2 b2 = *(const float2*)&bias[c];
#pragma unroll
            for (int hh2 = 0; hh2 < 2; hh2++) {
                long long rr = (hh2 == 0) ? r1 : r2;
                if (rr < M) {
                    float vx = acc[i][j][hh2 * 2 + 0] + b2.x;
                    float vy = acc[i][j][hh2 * 2 + 1] + b2.y;
                    float2 d = *(const float2*)&Dz[rr * 256 + c];
                    vx += d.x; vy += d.y;
                    *(float2*)&Cz[rr * 256 + c] = make_float2(vx, vy);
                }
            }
        }
    }
}

// ---------------------------------------------------------------------------
// CAT kernel (fp16 1-product): tile 64x128, BK=64, 256 threads (8 warps
// 2m x 4n, warp tile 32x32), 2 CTAs/SM.
// A[r,k] = rn16(concat(A1, A2*invdeg)[r,k]);  C = A @ Bf^T + bias.
// Optional transposed output Cout[c*CtS + r].
// ---------------------------------------------------------------------------
#define AH_T 9216                     // 64 * 144
#define BH_T 18432                    // 128 * 144
#define STG1 (AH_T + BH_T)            // 27648
#define GS1  (2 * STG1)               // 55296

__global__ __launch_bounds__(256, 2) void cat_kernel(
    const float* __restrict__ A1, const float* __restrict__ A2, int K1,
    const float* __restrict__ deg,
    const __half* __restrict__ Bf,
    const float* __restrict__ bias,
    float* __restrict__ Cout, long long CtS, int trans_out,
    int M, int K)
{
    extern __shared__ char smem[];
    const uint32_t sb = smem_u32(smem);
    const int tid = threadIdx.x;
    const int wid = tid >> 5;
    const int lane = tid & 31;
    const int warp_m = wid >> 2;       // 0..1
    const int warp_n = wid & 3;        // 0..3
    const long long m0 = (long long)blockIdx.x * 64;
    const int n0 = blockIdx.y * 128;

    float acc[2][4][4];
#pragma unroll
    for (int i = 0; i < 2; i++)
#pragma unroll
        for (int j = 0; j < 4; j++)
#pragma unroll
            for (int p = 0; p < 4; p++) acc[i][j][p] = 0.f;

    const int nK = K / 64;
    const int q = tid >> 6;
    const int r = tid & 63;
    const long long rg1 = m0 + r;
    const bool rowok = (rg1 < M);

    float a16[16];

    const uint32_t aoff = (uint32_t)(warp_m * 32 + (lane & 15)) * ROWB +
                          (uint32_t)((lane >> 4) << 3) * 2;
    const uint32_t boff = (uint32_t)(warp_n * 32 + ((lane >> 4) << 3) + (lane & 7)) * ROWB +
                          (uint32_t)(((lane >> 3) & 1) << 3) * 2;

    auto cpB = [&](int kt, int stage) {
        const int k0 = kt * 64;
        const uint32_t base = sb + stage * STG1 + AH_T;
#pragma unroll
        for (int i = 0; i < 4; i++) {
            int idx = tid + 256 * i;
            int n  = idx >> 3;
            int kq = idx & 7;
            uint32_t dst = base + (uint32_t)n * ROWB + (uint32_t)kq * 16;
            long long soff = (long long)(n0 + n) * K + k0 + kq * 8;
            CP16(dst, Bf + soff);
        }
    };

    auto prefA = [&](int kt) {
        const int kg = kt * 64 + q * 16;
        if (rowok) {
            bool second = (kg >= K1);
            const float* src = second ? &A2[rg1 * (long long)(K - K1) + (kg - K1)]
                                      : &A1[rg1 * (long long)K1 + kg];
#pragma unroll
            for (int f = 0; f < 4; f++)
                *(float4*)&a16[f * 4] = ((const float4*)src)[f];
            if (second && deg) {
                float inv = 1.0f / fmaxf(deg[rg1], 1.0f);
#pragma unroll
                for (int d = 0; d < 16; d++) a16[d] *= inv;
            }
        } else {
#pragma unroll
            for (int d = 0; d < 16; d++) a16[d] = 0.f;
        }
    };

    auto produceA = [&](int stage) {
        const uint32_t off = (uint32_t)stage * STG1 + (uint32_t)r * ROWB + (uint32_t)q * 32;
        uint32_t u[8];
#pragma unroll
        for (int d2 = 0; d2 < 8; d2++)
            u[d2] = pack2h(a16[d2 * 2], a16[d2 * 2 + 1]);
        *(uint4*)(smem + off)      = make_uint4(u[0], u[1], u[2], u[3]);
        *(uint4*)(smem + off + 16) = make_uint4(u[4], u[5], u[6], u[7]);
    };

    auto compute = [&](int stage) {
        const uint32_t base = sb + stage * STG1;
#pragma unroll
        for (int ks = 0; ks < 4; ks++) {
            const uint32_t kk = (uint32_t)ks * 32;
            uint32_t a_h[2][4];
#pragma unroll
            for (int i = 0; i < 2; i++) {
                uint32_t ad = base + aoff + (uint32_t)(i * 16) * ROWB + kk;
                LDSM_X4(a_h[i][0], a_h[i][1], a_h[i][2], a_h[i][3], ad);
            }
            uint32_t b_h[8];
#pragma unroll
            for (int jj = 0; jj < 2; jj++) {
                uint32_t bd = base + AH_T + boff + (uint32_t)(jj * 16) * ROWB + kk;
                LDSM_X4(b_h[jj * 4 + 0], b_h[jj * 4 + 1], b_h[jj * 4 + 2], b_h[jj * 4 + 3], bd);
            }
#pragma unroll
            for (int i = 0; i < 2; i++)
#pragma unroll
                for (int j = 0; j < 4; j++)
                    MMA_F16(acc[i][j], a_h[i], b_h[j * 2], b_h[j * 2 + 1]);
        }
    };

    prefA(0);
    cpB(0, 0);
    CP_COMMIT();
    produceA(0);
    CP_WAIT0();
    __syncthreads();

    for (int kt = 0; kt < nK; kt++) {
        const int cur = kt & 1;
        const bool more = (kt + 1 < nK);
        if (more) {
            prefA(kt + 1);
            cpB(kt + 1, cur ^ 1);
            CP_COMMIT();
        }
        compute(cur);
        if (more) produceA(cur ^ 1);
        CP_WAIT0();
        __syncthreads();
    }

#pragma unroll
    for (int i = 0; i < 2; i++) {
        long long r1 = m0 + warp_m * 32 + i * 16 + (lane >> 2);
        long long r2 = r1 + 8;
#pragma unroll
        for (int j = 0; j < 4; j++) {
            int c = n0 + warp_n * 32 + j * 8 + (lane & 3) * 2;
            float2 b2 = *(const float2*)&bias[c];
#pragma unroll
            for (int hh2 = 0; hh2 < 2; hh2++) {
                long long rr = (hh2 == 0) ? r1 : r2;
                if (rr < M) {
                    float vx = acc[i][j][hh2 * 2 + 0] + b2.x;
                    float vy = acc[i][j][hh2 * 2 + 1] + b2.y;
                    if (trans_out) {
                        Cout[(long long)c * CtS + rr]       = vx;
                        Cout[(long long)(c + 1) * CtS + rr] = vy;
                    } else {
                        *(float2*)&Cout[rr * 256 + c] = make_float2(vx, vy);
                    }
                }
            }
        }
    }
}

// ---------------------------------------------------------------------------
// fp32 SGEMM for the small output head (N=64)
// ---------------------------------------------------------------------------
#define BMH 128
#define BNH 128
#define BKH 8

__global__ __launch_bounds__(256) void sgemm_kernel(
    const float* __restrict__ A, const float* __restrict__ B,
    const float* __restrict__ bias, float* __restrict__ C, int M, int N, int K)
{
    __shared__ float As[BKH][BMH];
    __shared__ float Bs[BKH][BNH];
    int row0 = blockIdx.y * BMH;
    int col0 = blockIdx.x * BNH;
    int tid = threadIdx.x;
    int aRow = tid >> 1;
    int aCol = (tid & 1) * 4;
    int bRow = tid >> 5;
    int bCol = (tid & 31) * 4;
    int tx = tid & 15;
    int ty = tid >> 4;
    float acc[8][8];
#pragma unroll
    for (int i = 0; i < 8; i++)
#pragma unroll
        for (int j = 0; j < 8; j++) acc[i][j] = 0.f;
    int nK = K / BKH;
    for (int kt = 0; kt < nK; ++kt) {
        int k0 = kt * BKH;
        float4 av = make_float4(0.f, 0.f, 0.f, 0.f);
        int gr = row0 + aRow;
        if (gr < M) av = *(const float4*)&A[(long long)gr * K + k0 + aCol];
        As[aCol + 0][aRow] = av.x;
        As[aCol + 1][aRow] = av.y;
        As[aCol + 2][aRow] = av.z;
        As[aCol + 3][aRow] = av.w;
        float4 bv = make_float4(0.f, 0.f, 0.f, 0.f);
        int gc = col0 + bCol;
        if (gc < N) bv = *(const float4*)&B[(long long)(k0 + bRow) * N + gc];
        *(float4*)&Bs[bRow][bCol] = bv;
        __syncthreads();
#pragma unroll
        for (int k = 0; k < BKH; k++) {
            float ar[8], br[8];
#pragma unroll
            for (int i = 0; i < 8; i++) ar[i] = As[k][ty * 8 + i];
#pragma unroll
            for (int j = 0; j < 8; j++) br[j] = Bs[k][tx * 8 + j];
#pragma unroll
            for (int i = 0; i < 8; i++)
#pragma unroll
                for (int j = 0; j < 8; j++) acc[i][j] += ar[i] * br[j];
        }
        __syncthreads();
    }
#pragma unroll
    for (int i = 0; i < 8; i++) {
        int r = row0 + ty * 8 + i;
        if (r >= M) continue;
#pragma unroll
        for (int j = 0; j < 8; j++) {
            int c = col0 + tx * 8 + j;
            if (c >= N) continue;
            C[(long long)r * N + c] = acc[i][j] + bias[c];
        }
    }
}

// ---------------------------------------------------------------------------
// Host helpers
// ---------------------------------------------------------------------------
static void zero_buf(float* p, long long n_floats) {
    zero_kernel<<<1024, 256>>>((float4*)p, n_floats / 4);
}

static void gemm_cat(const float* A1, const float* A2, int K1, const float* deg,
                     const __half* Bf,
                     const float* bias, float* C, long long CtS, int trans,
                     int M, int K) {
    dim3 grid((M + 63) / 64, 2, 1);
    cat_kernel<<<grid, 256, GS1>>>(A1, A2, K1, deg, Bf, bias, C, CtS, trans, M, K);
}

static void gemm_mix(const float* hT, const float* lam, const float* Bp, int tfix,
                     const __half* Bf,
                     const float* bias, const float* Dadd, long long DzS,
                     float* C, long long CzS, int M, int K, int nz) {
    dim3 grid((M + 63) / 64, 1, nz);
    mix_kernel<<<grid, 512, GS0>>>(hT, lam, Bp, tfix, Bf, bias, Dadd, DzS,
                                   C, CzS, M, K);
}

// ---------------------------------------------------------------------------
// Launch
// ---------------------------------------------------------------------------
extern "C" void kernel_launch(void* const* d_in, const int* in_sizes, int n_in,
                              void* d_out, int out_size) {
    const float* xs      = (const float*)d_in[0];
    const void*  ei      = d_in[1];
    const float* w_pre   = (const float*)d_in[2];
    const float* b_pre   = (const float*)d_in[3];

    const float* w_res0  = (const float*)d_in[4];
    const float* b_res0  = (const float*)d_in[5];
    const float* w_self0 = (const float*)d_in[6];
    const float* w_neigh0= (const float*)d_in[7];
    const float* b_sage0 = (const float*)d_in[8];
    const float* a_log0  = (const float*)d_in[9];
    const float* B0      = (const float*)d_in[10];
    const float* w_mix0  = (const float*)d_in[11];
    const float* b_mix0  = (const float*)d_in[12];

    const float* w_res1  = (const float*)d_in[13];
    const float* b_res1  = (const float*)d_in[14];
    const float* w_self1 = (const float*)d_in[15];
    const float* w_neigh1= (const float*)d_in[16];
    const float* b_sage1 = (const float*)d_in[17];
    const float* a_log1  = (const float*)d_in[18];
    const float* B1      = (const float*)d_in[19];
    const float* w_mix1  = (const float*)d_in[20];
    const float* b_mix1  = (const float*)d_in[21];

    const float* w_out   = (const float*)d_in[22];
    const float* b_out   = (const float*)d_in[23];

    float *x0, *x1, *hT, *xsr, *agg, *deg, *lam, *xlast, *xsrl;
    cudaGetSymbolAddress((void**)&x0,    g_x0);
    cudaGetSymbolAddress((void**)&x1,    g_x1);
    cudaGetSymbolAddress((void**)&hT,    g_hT);
    cudaGetSymbolAddress((void**)&xsr,   g_xsr);
    cudaGetSymbolAddress((void**)&agg,   g_agg);
    cudaGetSymbolAddress((void**)&deg,   g_deg);
    cudaGetSymbolAddress((void**)&lam,   g_lam);
    cudaGetSymbolAddress((void**)&xlast, g_xlast);
    cudaGetSymbolAddress((void**)&xsrl,  g_xsrl);

    __half *cat0f, *cat1f, *res0f, *res1f, *mix0f, *mix1f;
    cudaGetSymbolAddress((void**)&cat0f, g_cat0_f);
    cudaGetSymbolAddress((void**)&cat1f, g_cat1_f);
    cudaGetSymbolAddress((void**)&res0f, g_res0_f);
    cudaGetSymbolAddress((void**)&res1f, g_res1_f);
    cudaGetSymbolAddress((void**)&mix0f, g_mix0_f);
    cudaGetSymbolAddress((void**)&mix1f, g_mix1_f);

    cudaFuncSetAttribute(mix_kernel,
                         cudaFuncAttributeMaxDynamicSharedMemorySize, GS0);
    cudaFuncSetAttribute(cat_kernel,
                         cudaFuncAttributeMaxDynamicSharedMemorySize, GS1);

    auto fw = [](const float* w1, const float* w2, int K1, int Kt, __half* out) {
        long long tot = (long long)Kt * 256;
        f16w_kernel<<<(int)((tot + 255) / 256), 256>>>(w1, w2, K1, Kt, out);
    };

    // Launch order: 5th launch is the layer-0 scatter (profiled slot).
    detect_kernel<<<1, 32>>>((const unsigned int*)ei);                        // 1
    lam_kernel<<<(2 * HD + 255) / 256, 256>>>(a_log0, a_log1, lam);           // 2
    token_mix_kernel<<<(TV * C_IN + 255) / 256, 256>>>(xs, w_pre, b_pre, x0); // 3
    zero2_kernel<<<1024, 256>>>((float4*)agg, (long long)TV * C_IN / 4,
                                (float4*)deg, (long long)TV / 4);             // 4
    {
        long long tot = (long long)T * E * (C_IN / 4);
        scatter_kernel<<<(int)((tot + 255) / 256), 256>>>(x0, ei, agg, deg, C_IN); // 5
    }
    fw(w_self0, w_neigh0, C_IN, 2 * C_IN, cat0f);
    fw(w_self1, w_neigh1, H, 2 * H, cat1f);
    fw(w_res0, nullptr, C_IN, C_IN, res0f);
    fw(w_res1, nullptr, H, H, res1f);
    fw(w_mix0, nullptr, HD, HD, mix0f);
    fw(w_mix1, nullptr, HD, HD, mix1f);

    // ---------------- layer 0 ----------------
    gemm_cat(x0, agg, C_IN, deg, cat0f, b_sage0, hT, TV, 1, TV, 2 * C_IN);
    gemm_cat(x0, x0,  C_IN, nullptr, res0f, b_res0, xsr, 0, 0, TV, C_IN);

    // all 8 mix0 GEMMs, scan fused in producer (ts = z+1), full-N tile
    gemm_mix(hT, lam, B0, 0, mix0f, b_mix0,
             xsr, (long long)V * H, x1, (long long)V * H, V, HD, T);

    // ---------------- layer 1 ----------------
    zero_buf(agg, (long long)TV * H);
    {
        long long tot = (long long)T * E * (H / 4);
        scatter_kernel<<<(int)((tot + 255) / 256), 256>>>(x1, ei, agg, nullptr, H);
    }
    gemm_cat(x1, agg, H, deg, cat1f, b_sage1, hT, TV, 1, TV, 2 * H);
    gemm_cat(x1 + (long long)(T - 1) * V * H, x1 + (long long)(T - 1) * V * H, H,
             nullptr, res1f, b_res1, xsrl, 0, 0, V, H);

    // mix1: full 8-step scan, single z (xsrl as Dadd slot 0)
    gemm_mix(hT, lam + HD, B1, T, mix1f, b_mix1,
             xsrl, 0, xlast, 0, V, HD, 1);

    // ---------------- output head ----------------
    dim3 og((C_OUT + BNH - 1) / BNH, (V + BMH - 1) / BMH);
    sgemm_kernel<<<og, 256>>>(xlast, w_out, b_out, (float*)d_out, V, C_OUT, H);
}

// round 15
// speedup vs baseline: 2.9973x; 1.0683x over previous
#include <cuda_runtime.h>
#include <cuda_bf16.h>
#include <cuda_fp16.h>
#include <cstdint>

#define T 8
#define V 10000
#define E 100000
#define C_IN 128
#define H 256
#define DS 16
#define C_OUT 64
#define HD (H * DS)          // 4096
#define TV (T * V)           // 80000

// ---------------------------------------------------------------------------
// Scratch (device globals; no allocation allowed)
// ---------------------------------------------------------------------------
__device__ __align__(128) float g_x0[(size_t)TV * C_IN];
__device__ __align__(128) float g_x1[(size_t)TV * H];
__device__ __align__(128) float g_hT[(size_t)H * TV];   // sage output, [hh][t][v]
__device__ __align__(128) float g_xsr[(size_t)TV * H];
__device__ __align__(128) float g_agg[(size_t)TV * H];
__device__ __align__(128) float g_deg[(size_t)TV];
__device__ __align__(128) float g_lam[2 * HD];
__device__ __align__(128) float g_xlast[(size_t)V * H];
__device__ __align__(128) float g_xsrl [(size_t)V * H];
__device__ int g_is64;

// fp16 single-plane transposed weights ([N=256][K], K-major)
__device__ __align__(128) __half g_cat0_f[256 * 256];
__device__ __align__(128) __half g_cat1_f[256 * 512];
__device__ __align__(128) __half g_res0_f[256 * 128];
__device__ __align__(128) __half g_res1_f[256 * 256];
__device__ __align__(128) __half g_mix0_f[256 * HD];
__device__ __align__(128) __half g_mix1_f[256 * HD];

// ---------------------------------------------------------------------------
// Helpers
// ---------------------------------------------------------------------------
__device__ __forceinline__ uint32_t smem_u32(const void* p) {
    uint32_t a;
    asm("{ .reg .u64 t; cvta.to.shared.u64 t, %1; cvt.u32.u64 %0, t; }" : "=r"(a) : "l"(p));
    return a;
}

__device__ __forceinline__ uint32_t pack2h(float a, float b) {
    __half h0 = __float2half_rn(a);
    __half h1 = __float2half_rn(b);
    return (uint32_t)__half_as_ushort(h0) | ((uint32_t)__half_as_ushort(h1) << 16);
}

#define LDSM_X4(r0, r1, r2, r3, addr) \
    asm volatile("ldmatrix.sync.aligned.m8n8.x4.shared.b16 {%0,%1,%2,%3}, [%4];" \
        : "=r"(r0), "=r"(r1), "=r"(r2), "=r"(r3) : "r"(addr))

#define MMA_F16(d, a, b0, b1) \
    asm volatile("mma.sync.aligned.m16n8k16.row.col.f32.f16.f16.f32 " \
        "{%0,%1,%2,%3}, {%4,%5,%6,%7}, {%8,%9}, {%0,%1,%2,%3};" \
        : "+f"((d)[0]), "+f"((d)[1]), "+f"((d)[2]), "+f"((d)[3]) \
        : "r"((a)[0]), "r"((a)[1]), "r"((a)[2]), "r"((a)[3]), "r"(b0), "r"(b1))

#define CP16(dst, src) \
    asm volatile("cp.async.cg.shared.global [%0], [%1], 16;" :: "r"(dst), "l"(src))
#define CP_COMMIT() asm volatile("cp.async.commit_group;" ::: "memory")
#define CP_WAIT0()  asm volatile("cp.async.wait_group 0;" ::: "memory")

// ---------------------------------------------------------------------------
// Small kernels
// ---------------------------------------------------------------------------
__global__ void zero_kernel(float4* p, long long n4) {
    long long i = blockIdx.x * (long long)blockDim.x + threadIdx.x;
    long long stride = (long long)gridDim.x * blockDim.x;
    for (; i < n4; i += stride) p[i] = make_float4(0.f, 0.f, 0.f, 0.f);
}

// zero two buffers in one launch
__global__ void zero2_kernel(float4* p1, long long n1, float4* p2, long long n2) {
    long long i = blockIdx.x * (long long)blockDim.x + threadIdx.x;
    long long stride = (long long)gridDim.x * blockDim.x;
    const float4 zz = make_float4(0.f, 0.f, 0.f, 0.f);
    for (long long j = i; j < n1; j += stride) p1[j] = zz;
    for (long long j = i; j < n2; j += stride) p2[j] = zz;
}

__global__ void detect_kernel(const unsigned int* ei) {
    if (threadIdx.x == 0 && blockIdx.x == 0) {
        unsigned int s = 0;
        for (int i = 0; i < 64; i++) s |= ei[2 * i + 1];
        g_is64 = (s == 0) ? 1 : 0;
    }
}

__device__ __forceinline__ int load_edge(const void* ei, long long pos) {
    if (g_is64) return (int)((const long long*)ei)[pos];
    return ((const int*)ei)[pos];
}

__global__ void lam_kernel(const float* a0, const float* a1, float* lam) {
    int i = blockIdx.x * blockDim.x + threadIdx.x;
    if (i < HD)           lam[i] = expf(-expf(a0[i]));
    else if (i < 2 * HD)  lam[i] = expf(-expf(a1[i - HD]));
}

__global__ void token_mix_kernel(const float* __restrict__ xs,
                                 const float* __restrict__ w,
                                 const float* __restrict__ b,
                                 float* __restrict__ out) {
    int idx = blockIdx.x * blockDim.x + threadIdx.x;
    if (idx >= TV * C_IN) return;
    int c = idx % C_IN;
    int t = idx / (V * C_IN);
    float acc = b[c] + xs[idx] * w[c * 3 + 1];
    if (t > 0)     acc += xs[idx - V * C_IN] * w[c * 3 + 0];
    if (t < T - 1) acc += xs[idx + V * C_IN] * w[c * 3 + 2];
    out[idx] = acc;
}

// ---------------------------------------------------------------------------
// Scatter v2: one thread per (edge, group-lane); GROUP lanes cover the row,
// each lane handles NPASS float4 chunks strided by GROUP (coalesced).
// GROUP*NPASS*4 == C.  deg accumulated once per edge by lane 0.
// ---------------------------------------------------------------------------
template <int GROUP, int NPASS, int C>
__global__ void scatter2_kernel(const float* __restrict__ x, const void* __restrict__ ei,
                                float* __restrict__ agg, float* __restrict__ deg) {
    long long idx = blockIdx.x * (long long)blockDim.x + threadIdx.x;
    long long total = (long long)T * E * GROUP;
    if (idx >= total) return;
    int lane = (int)(idx % GROUP);
    long long te = idx / GROUP;
    int e = (int)(te % E);
    int t = (int)(te / E);
    long long base = (long long)t * 2 * E;
    int src = load_edge(ei, base + e);
    int dst = load_edge(ei, base + E + e);
    const float* xr = &x[((long long)t * V + src) * C];
    float* ar = &agg[((long long)t * V + dst) * C];
#pragma unroll
    for (int p = 0; p < NPASS; p++) {
        int c4 = lane + p * GROUP;
        float4 v = *(const float4*)&xr[c4 * 4];
        asm volatile("red.global.add.v4.f32 [%0], {%1,%2,%3,%4};"
                     :: "l"(&ar[c4 * 4]), "f"(v.x), "f"(v.y), "f"(v.z), "f"(v.w)
                     : "memory");
    }
    if (deg && lane == 0) {
        float* dp = &deg[(long long)t * V + dst];
        asm volatile("red.global.add.f32 [%0], %1;" :: "l"(dp), "f"(1.0f) : "memory");
    }
}

// Build transposed fp16 weights: dst[n][k] = rn(concat(w1,w2)[k][n])
__global__ void f16w_kernel(const float* __restrict__ w1, const float* __restrict__ w2,
                            int K1, int Kt, __half* __restrict__ out) {
    long long idx = blockIdx.x * (long long)blockDim.x + threadIdx.x;
    if (idx >= (long long)Kt * 256) return;
    int k = (int)(idx % Kt);
    int n = (int)(idx / Kt);
    float v = (k < K1) ? w1[(long long)k * 256 + n] : w2[(long long)(k - K1) * 256 + n];
    out[(long long)n * Kt + k] = __float2half_rn(v);
}

// ---------------------------------------------------------------------------
// Shared GEMM geometry constants
// ---------------------------------------------------------------------------
#define ROWB 144                      // 64 k * 2B + 16 pad

// ---------------------------------------------------------------------------
// MIX kernel (scan-fused, fp16 1-product): tile 64x256 (FULL N, grid_y=1),
// BK=64, 512 threads (16 warps 2m x 8n, warp tile 32x32), 1 CTA/SM.
// ---------------------------------------------------------------------------
#define A_T0 9216                     // 64 * 144
#define B_T0 36864                    // 256 * 144
#define STG0 (A_T0 + B_T0)            // 46080
#define LAM0 (2 * STG0)               // 92160
#define GS0  (LAM0 + 32768)           // 124928

__global__ __launch_bounds__(512, 1) void mix_kernel(
    const float* __restrict__ hT, const float* __restrict__ lam,
    const float* __restrict__ Bp, int tfix,
    const __half* __restrict__ Bf,
    const float* __restrict__ bias,
    const float* __restrict__ Dadd, long long DzS,
    float* __restrict__ Cout, long long CzS,
    int M, int K)
{
    extern __shared__ char smem[];
    const uint32_t sb = smem_u32(smem);
    const int tid = threadIdx.x;
    const int wid = tid >> 5;
    const int lane = tid & 31;
    const int warp_m = wid >> 3;       // 0..1
    const int warp_n = wid & 7;        // 0..7
    const int z = blockIdx.z;
    const long long m0 = (long long)blockIdx.x * 64;

    const float* Dz = Dadd + (long long)z * DzS;
    float* Cz = Cout + (long long)z * CzS;

    float acc[2][4][4];
#pragma unroll
    for (int i = 0; i < 2; i++)
#pragma unroll
        for (int j = 0; j < 4; j++)
#pragma unroll
            for (int p = 0; p < 4; p++) acc[i][j][p] = 0.f;

    const int nK = K / 64;
    const int ts = (tfix > 0) ? tfix : z + 1;

    const int q = (tid & 255) >> 6;
    const int r = tid & 63;
    const long long rg1 = m0 + r;
    const bool produce = (tid < 256);
    const bool rowok = (rg1 < M);

    float hx[8];

    const uint32_t aoff = (uint32_t)(warp_m * 32 + (lane & 15)) * ROWB +
                          (uint32_t)((lane >> 4) << 3) * 2;
    const uint32_t boff = (uint32_t)(warp_n * 32 + ((lane >> 4) << 3) + (lane & 7)) * ROWB +
                          (uint32_t)(((lane >> 3) & 1) << 3) * 2;

#pragma unroll
    for (int j = 0; j < 2; j++) {
        int idx = tid + 512 * j;       // 0..1023
        *(float4*)(smem + LAM0 + idx * 16)         = ((const float4*)lam)[idx];
        *(float4*)(smem + LAM0 + 16384 + idx * 16) = ((const float4*)Bp)[idx];
    }

    auto cpB = [&](int kt, int stage) {
        const int k0 = kt * 64;
        const uint32_t base = sb + stage * STG0 + A_T0;
#pragma unroll
        for (int i = 0; i < 4; i++) {
            int idx = tid + 512 * i;   // 0..2047
            int n  = idx >> 3;         // 0..255
            int kq = idx & 7;
            uint32_t dst = base + (uint32_t)n * ROWB + (uint32_t)kq * 16;
            long long soff = (long long)n * K + k0 + kq * 8;
            CP16(dst, Bf + soff);
        }
    };

    auto prefA = [&](int kt) {
        if (!produce) return;
        const int hh = (kt * 64 + q * 16) >> 4;
        const long long hb = (long long)hh * TV + rg1;
#pragma unroll
        for (int tt = 0; tt < 8; tt++)
            hx[tt] = (rowok && tt < ts) ? hT[hb + (long long)tt * V] : 0.f;
    };

    auto produceA = [&](int stage, int kt) {
        if (!produce) return;
        const uint32_t off = (uint32_t)stage * STG0 + (uint32_t)r * ROWB + (uint32_t)q * 32;
        const int kg = kt * 64 + q * 16;
        float lam16[16], b16[16];
#pragma unroll
        for (int f = 0; f < 4; f++) {
            *(float4*)&lam16[f * 4] = *(const float4*)(smem + LAM0 + kg * 4 + f * 16);
            *(float4*)&b16[f * 4]   = *(const float4*)(smem + LAM0 + 16384 + kg * 4 + f * 16);
        }
        float s[16];
#pragma unroll
        for (int d = 0; d < 16; d++) s[d] = 0.f;
#pragma unroll
        for (int tt = 0; tt < 8; tt++) {
            if (tt < ts) {
                float x = hx[tt];
#pragma unroll
                for (int d = 0; d < 16; d++) s[d] = lam16[d] * s[d] + x * b16[d];
            }
        }
        uint32_t u[8];
#pragma unroll
        for (int d2 = 0; d2 < 8; d2++)
            u[d2] = pack2h(fmaxf(s[d2 * 2], 0.f), fmaxf(s[d2 * 2 + 1], 0.f));
        *(uint4*)(smem + off)      = make_uint4(u[0], u[1], u[2], u[3]);
        *(uint4*)(smem + off + 16) = make_uint4(u[4], u[5], u[6], u[7]);
    };

    auto compute = [&](int stage) {
        const uint32_t base = sb + stage * STG0;
#pragma unroll
        for (int ks = 0; ks < 4; ks++) {
            const uint32_t kk = (uint32_t)ks * 32;
            uint32_t a_h[2][4];
#pragma unroll
            for (int i = 0; i < 2; i++) {
                uint32_t ad = base + aoff + (uint32_t)(i * 16) * ROWB + kk;
                LDSM_X4(a_h[i][0], a_h[i][1], a_h[i][2], a_h[i][3], ad);
            }
            uint32_t b_h[8];
#pragma unroll
            for (int jj = 0; jj < 2; jj++) {
                uint32_t bd = base + A_T0 + boff + (uint32_t)(jj * 16) * ROWB + kk;
                LDSM_X4(b_h[jj * 4 + 0], b_h[jj * 4 + 1], b_h[jj * 4 + 2], b_h[jj * 4 + 3], bd);
            }
#pragma unroll
            for (int i = 0; i < 2; i++)
#pragma unroll
                for (int j = 0; j < 4; j++)
                    MMA_F16(acc[i][j], a_h[i], b_h[j * 2], b_h[j * 2 + 1]);
        }
    };

    prefA(0);
    cpB(0, 0);
    CP_COMMIT();
    __syncthreads();                   // lam/Bp smem visible
    produceA(0, 0);
    CP_WAIT0();
    __syncthreads();

    for (int kt = 0; kt < nK; kt++) {
        const int cur = kt & 1;
        const bool more = (kt + 1 < nK);
        if (more) {
            prefA(kt + 1);
            cpB(kt + 1, cur ^ 1);
            CP_COMMIT();
        }
        compute(cur);
        if (more) produceA(cur ^ 1, kt + 1);
        CP_WAIT0();
        __syncthreads();
    }

#pragma unroll
    for (int i = 0; i < 2; i++) {
        long long r1 = m0 + warp_m * 32 + i * 16 + (lane >> 2);
        long long r2 = r1 + 8;
#pragma unroll
        for (int j = 0; j < 4; j++) {
            int c = warp_n * 32 + j * 8 + (lane & 3) * 2;
            float2 b2 = *(const float2*)&bias[c];
#pragma unroll
            for (int hh2 = 0; hh2 < 2; hh2++) {
                long long rr = (hh2 == 0) ? r1 : r2;
                if (rr < M) {
                    float vx = acc[i][j][hh2 * 2 + 0] + b2.x;
                    float vy = acc[i][j][hh2 * 2 + 1] + b2.y;
                    float2 d = *(const float2*)&Dz[rr * 256 + c];
                    vx += d.x; vy += d.y;
                    *(float2*)&Cz[rr * 256 + c] = make_float2(vx, vy);
                }
            }
        }
    }
}

// ---------------------------------------------------------------------------
// CAT kernel (fp16 1-product): tile 64x128, BK=64, 256 threads, 2 CTAs/SM.
// ---------------------------------------------------------------------------
#define AH_T 9216                     // 64 * 144
#define BH_T 18432                    // 128 * 144
#define STG1 (AH_T + BH_T)            // 27648
#define GS1  (2 * STG1)               // 55296

__global__ __launch_bounds__(256, 2) void cat_kernel(
    const float* __restrict__ A1, const float* __restrict__ A2, int K1,
    const float* __restrict__ deg,
    const __half* __restrict__ Bf,
    const float* __restrict__ bias,
    float* __restrict__ Cout, long long CtS, int trans_out,
    int M, int K)
{
    extern __shared__ char smem[];
    const uint32_t sb = smem_u32(smem);
    const int tid = threadIdx.x;
    const int wid = tid >> 5;
    const int lane = tid & 31;
    const int warp_m = wid >> 2;       // 0..1
    const int warp_n = wid & 3;        // 0..3
    const long long m0 = (long long)blockIdx.x * 64;
    const int n0 = blockIdx.y * 128;

    float acc[2][4][4];
#pragma unroll
    for (int i = 0; i < 2; i++)
#pragma unroll
        for (int j = 0; j < 4; j++)
#pragma unroll
            for (int p = 0; p < 4; p++) acc[i][j][p] = 0.f;

    const int nK = K / 64;
    const int q = tid >> 6;
    const int r = tid & 63;
    const long long rg1 = m0 + r;
    const bool rowok = (rg1 < M);

    float a16[16];

    const uint32_t aoff = (uint32_t)(warp_m * 32 + (lane & 15)) * ROWB +
                          (uint32_t)((lane >> 4) << 3) * 2;
    const uint32_t boff = (uint32_t)(warp_n * 32 + ((lane >> 4) << 3) + (lane & 7)) * ROWB +
                          (uint32_t)(((lane >> 3) & 1) << 3) * 2;

    auto cpB = [&](int kt, int stage) {
        const int k0 = kt * 64;
        const uint32_t base = sb + stage * STG1 + AH_T;
#pragma unroll
        for (int i = 0; i < 4; i++) {
            int idx = tid + 256 * i;
            int n  = idx >> 3;
            int kq = idx & 7;
            uint32_t dst = base + (uint32_t)n * ROWB + (uint32_t)kq * 16;
            long long soff = (long long)(n0 + n) * K + k0 + kq * 8;
            CP16(dst, Bf + soff);
        }
    };

    auto prefA = [&](int kt) {
        const int kg = kt * 64 + q * 16;
        if (rowok) {
            bool second = (kg >= K1);
            const float* src = second ? &A2[rg1 * (long long)(K - K1) + (kg - K1)]
                                      : &A1[rg1 * (long long)K1 + kg];
#pragma unroll
            for (int f = 0; f < 4; f++)
                *(float4*)&a16[f * 4] = ((const float4*)src)[f];
            if (second && deg) {
                float inv = 1.0f / fmaxf(deg[rg1], 1.0f);
#pragma unroll
                for (int d = 0; d < 16; d++) a16[d] *= inv;
            }
        } else {
#pragma unroll
            for (int d = 0; d < 16; d++) a16[d] = 0.f;
        }
    };

    auto produceA = [&](int stage) {
        const uint32_t off = (uint32_t)stage * STG1 + (uint32_t)r * ROWB + (uint32_t)q * 32;
        uint32_t u[8];
#pragma unroll
        for (int d2 = 0; d2 < 8; d2++)
            u[d2] = pack2h(a16[d2 * 2], a16[d2 * 2 + 1]);
        *(uint4*)(smem + off)      = make_uint4(u[0], u[1], u[2], u[3]);
        *(uint4*)(smem + off + 16) = make_uint4(u[4], u[5], u[6], u[7]);
    };

    auto compute = [&](int stage) {
        const uint32_t base = sb + stage * STG1;
#pragma unroll
        for (int ks = 0; ks < 4; ks++) {
            const uint32_t kk = (uint32_t)ks * 32;
            uint32_t a_h[2][4];
#pragma unroll
            for (int i = 0; i < 2; i++) {
                uint32_t ad = base + aoff + (uint32_t)(i * 16) * ROWB + kk;
                LDSM_X4(a_h[i][0], a_h[i][1], a_h[i][2], a_h[i][3], ad);
            }
            uint32_t b_h[8];
#pragma unroll
            for (int jj = 0; jj < 2; jj++) {
                uint32_t bd = base + AH_T + boff + (uint32_t)(jj * 16) * ROWB + kk;
                LDSM_X4(b_h[jj * 4 + 0], b_h[jj * 4 + 1], b_h[jj * 4 + 2], b_h[jj * 4 + 3], bd);
            }
#pragma unroll
            for (int i = 0; i < 2; i++)
#pragma unroll
                for (int j = 0; j < 4; j++)
                    MMA_F16(acc[i][j], a_h[i], b_h[j * 2], b_h[j * 2 + 1]);
        }
    };

    prefA(0);
    cpB(0, 0);
    CP_COMMIT();
    produceA(0);
    CP_WAIT0();
    __syncthreads();

    for (int kt = 0; kt < nK; kt++) {
        const int cur = kt & 1;
        const bool more = (kt + 1 < nK);
        if (more) {
            prefA(kt + 1);
            cpB(kt + 1, cur ^ 1);
            CP_COMMIT();
        }
        compute(cur);
        if (more) produceA(cur ^ 1);
        CP_WAIT0();
        __syncthreads();
    }

#pragma unroll
    for (int i = 0; i < 2; i++) {
        long long r1 = m0 + warp_m * 32 + i * 16 + (lane >> 2);
        long long r2 = r1 + 8;
#pragma unroll
        for (int j = 0; j < 4; j++) {
            int c = n0 + warp_n * 32 + j * 8 + (lane & 3) * 2;
            float2 b2 = *(const float2*)&bias[c];
#pragma unroll
            for (int hh2 = 0; hh2 < 2; hh2++) {
                long long rr = (hh2 == 0) ? r1 : r2;
                if (rr < M) {
                    float vx = acc[i][j][hh2 * 2 + 0] + b2.x;
                    float vy = acc[i][j][hh2 * 2 + 1] + b2.y;
                    if (trans_out) {
                        Cout[(long long)c * CtS + rr]       = vx;
                        Cout[(long long)(c + 1) * CtS + rr] = vy;
                    } else {
                        *(float2*)&Cout[rr * 256 + c] = make_float2(vx, vy);
                    }
                }
            }
        }
    }
}

// ---------------------------------------------------------------------------
// fp32 SGEMM for the small output head (N=64)
// ---------------------------------------------------------------------------
#define BMH 128
#define BNH 128
#define BKH 8

__global__ __launch_bounds__(256) void sgemm_kernel(
    const float* __restrict__ A, const float* __restrict__ B,
    const float* __restrict__ bias, float* __restrict__ C, int M, int N, int K)
{
    __shared__ float As[BKH][BMH];
    __shared__ float Bs[BKH][BNH];
    int row0 = blockIdx.y * BMH;
    int col0 = blockIdx.x * BNH;
    int tid = threadIdx.x;
    int aRow = tid >> 1;
    int aCol = (tid & 1) * 4;
    int bRow = tid >> 5;
    int bCol = (tid & 31) * 4;
    int tx = tid & 15;
    int ty = tid >> 4;
    float acc[8][8];
#pragma unroll
    for (int i = 0; i < 8; i++)
#pragma unroll
        for (int j = 0; j < 8; j++) acc[i][j] = 0.f;
    int nK = K / BKH;
    for (int kt = 0; kt < nK; ++kt) {
        int k0 = kt * BKH;
        float4 av = make_float4(0.f, 0.f, 0.f, 0.f);
        int gr = row0 + aRow;
        if (gr < M) av = *(const float4*)&A[(long long)gr * K + k0 + aCol];
        As[aCol + 0][aRow] = av.x;
        As[aCol + 1][aRow] = av.y;
        As[aCol + 2][aRow] = av.z;
        As[aCol + 3][aRow] = av.w;
        float4 bv = make_float4(0.f, 0.f, 0.f, 0.f);
        int gc = col0 + bCol;
        if (gc < N) bv = *(const float4*)&B[(long long)(k0 + bRow) * N + gc];
        *(float4*)&Bs[bRow][bCol] = bv;
        __syncthreads();
#pragma unroll
        for (int k = 0; k < BKH; k++) {
            float ar[8], br[8];
#pragma unroll
            for (int i = 0; i < 8; i++) ar[i] = As[k][ty * 8 + i];
#pragma unroll
            for (int j = 0; j < 8; j++) br[j] = Bs[k][tx * 8 + j];
#pragma unroll
            for (int i = 0; i < 8; i++)
#pragma unroll
                for (int j = 0; j < 8; j++) acc[i][j] += ar[i] * br[j];
        }
        __syncthreads();
    }
#pragma unroll
    for (int i = 0; i < 8; i++) {
        int r = row0 + ty * 8 + i;
        if (r >= M) continue;
#pragma unroll
        for (int j = 0; j < 8; j++) {
            int c = col0 + tx * 8 + j;
            if (c >= N) continue;
            C[(long long)r * N + c] = acc[i][j] + bias[c];
        }
    }
}

// ---------------------------------------------------------------------------
// Host helpers
// ---------------------------------------------------------------------------
static void zero_buf(float* p, long long n_floats) {
    zero_kernel<<<1024, 256>>>((float4*)p, n_floats / 4);
}

static void gemm_cat(const float* A1, const float* A2, int K1, const float* deg,
                     const __half* Bf,
                     const float* bias, float* C, long long CtS, int trans,
                     int M, int K) {
    dim3 grid((M + 63) / 64, 2, 1);
    cat_kernel<<<grid, 256, GS1>>>(A1, A2, K1, deg, Bf, bias, C, CtS, trans, M, K);
}

static void gemm_mix(const float* hT, const float* lam, const float* Bp, int tfix,
                     const __half* Bf,
                     const float* bias, const float* Dadd, long long DzS,
                     float* C, long long CzS, int M, int K, int nz) {
    dim3 grid((M + 63) / 64, 1, nz);
    mix_kernel<<<grid, 512, GS0>>>(hT, lam, Bp, tfix, Bf, bias, Dadd, DzS,
                                   C, CzS, M, K);
}

// ---------------------------------------------------------------------------
// Launch
// ---------------------------------------------------------------------------
extern "C" void kernel_launch(void* const* d_in, const int* in_sizes, int n_in,
                              void* d_out, int out_size) {
    const float* xs      = (const float*)d_in[0];
    const void*  ei      = d_in[1];
    const float* w_pre   = (const float*)d_in[2];
    const float* b_pre   = (const float*)d_in[3];

    const float* w_res0  = (const float*)d_in[4];
    const float* b_res0  = (const float*)d_in[5];
    const float* w_self0 = (const float*)d_in[6];
    const float* w_neigh0= (const float*)d_in[7];
    const float* b_sage0 = (const float*)d_in[8];
    const float* a_log0  = (const float*)d_in[9];
    const float* B0      = (const float*)d_in[10];
    const float* w_mix0  = (const float*)d_in[11];
    const float* b_mix0  = (const float*)d_in[12];

    const float* w_res1  = (const float*)d_in[13];
    const float* b_res1  = (const float*)d_in[14];
    const float* w_self1 = (const float*)d_in[15];
    const float* w_neigh1= (const float*)d_in[16];
    const float* b_sage1 = (const float*)d_in[17];
    const float* a_log1  = (const float*)d_in[18];
    const float* B1      = (const float*)d_in[19];
    const float* w_mix1  = (const float*)d_in[20];
    const float* b_mix1  = (const float*)d_in[21];

    const float* w_out   = (const float*)d_in[22];
    const float* b_out   = (const float*)d_in[23];

    float *x0, *x1, *hT, *xsr, *agg, *deg, *lam, *xlast, *xsrl;
    cudaGetSymbolAddress((void**)&x0,    g_x0);
    cudaGetSymbolAddress((void**)&x1,    g_x1);
    cudaGetSymbolAddress((void**)&hT,    g_hT);
    cudaGetSymbolAddress((void**)&xsr,   g_xsr);
    cudaGetSymbolAddress((void**)&agg,   g_agg);
    cudaGetSymbolAddress((void**)&deg,   g_deg);
    cudaGetSymbolAddress((void**)&lam,   g_lam);
    cudaGetSymbolAddress((void**)&xlast, g_xlast);
    cudaGetSymbolAddress((void**)&xsrl,  g_xsrl);

    __half *cat0f, *cat1f, *res0f, *res1f, *mix0f, *mix1f;
    cudaGetSymbolAddress((void**)&cat0f, g_cat0_f);
    cudaGetSymbolAddress((void**)&cat1f, g_cat1_f);
    cudaGetSymbolAddress((void**)&res0f, g_res0_f);
    cudaGetSymbolAddress((void**)&res1f, g_res1_f);
    cudaGetSymbolAddress((void**)&mix0f, g_mix0_f);
    cudaGetSymbolAddress((void**)&mix1f, g_mix1_f);

    cudaFuncSetAttribute(mix_kernel,
                         cudaFuncAttributeMaxDynamicSharedMemorySize, GS0);
    cudaFuncSetAttribute(cat_kernel,
                         cudaFuncAttributeMaxDynamicSharedMemorySize, GS1);

    auto fw = [](const float* w1, const float* w2, int K1, int Kt, __half* out) {
        long long tot = (long long)Kt * 256;
        f16w_kernel<<<(int)((tot + 255) / 256), 256>>>(w1, w2, K1, Kt, out);
    };

    detect_kernel<<<1, 32>>>((const unsigned int*)ei);
    lam_kernel<<<(2 * HD + 255) / 256, 256>>>(a_log0, a_log1, lam);
    token_mix_kernel<<<(TV * C_IN + 255) / 256, 256>>>(xs, w_pre, b_pre, x0);
    zero2_kernel<<<1024, 256>>>((float4*)agg, (long long)TV * C_IN / 4,
                                (float4*)deg, (long long)TV / 4);
    {
        // layer-0 scatter: GROUP=8, NPASS=4 (C=128)
        long long tot = (long long)T * E * 8;
        scatter2_kernel<8, 4, C_IN><<<(int)((tot + 255) / 256), 256>>>(x0, ei, agg, deg);
    }
    fw(w_self0, w_neigh0, C_IN, 2 * C_IN, cat0f);
    fw(w_self1, w_neigh1, H, 2 * H, cat1f);
    fw(w_res0, nullptr, C_IN, C_IN, res0f);
    fw(w_res1, nullptr, H, H, res1f);
    fw(w_mix0, nullptr, HD, HD, mix0f);
    fw(w_mix1, nullptr, HD, HD, mix1f);

    // ---------------- layer 0 ----------------
    gemm_cat(x0, agg, C_IN, deg, cat0f, b_sage0, hT, TV, 1, TV, 2 * C_IN);
    gemm_cat(x0, x0,  C_IN, nullptr, res0f, b_res0, xsr, 0, 0, TV, C_IN);

    // all 8 mix0 GEMMs, scan fused in producer (ts = z+1), full-N tile
    gemm_mix(hT, lam, B0, 0, mix0f, b_mix0,
             xsr, (long long)V * H, x1, (long long)V * H, V, HD, T);

    // ---------------- layer 1 ----------------
    zero_buf(agg, (long long)TV * H);
    {
        // layer-1 scatter: GROUP=16, NPASS=4 (C=256)
        long long tot = (long long)T * E * 16;
        scatter2_kernel<16, 4, H><<<(int)((tot + 255) / 256), 256>>>(x1, ei, agg, nullptr);
    }
    gemm_cat(x1, agg, H, deg, cat1f, b_sage1, hT, TV, 1, TV, 2 * H);
    gemm_cat(x1 + (long long)(T - 1) * V * H, x1 + (long long)(T - 1) * V * H, H,
             nullptr, res1f, b_res1, xsrl, 0, 0, V, H);

    // mix1: full 8-step scan, single z (xsrl as Dadd slot 0)
    gemm_mix(hT, lam + HD, B1, T, mix1f, b_mix1,
             xsrl, 0, xlast, 0, V, HD, 1);

    // ---------------- output head ----------------
    dim3 og((C_OUT + BNH - 1) / BNH, (V + BMH - 1) / BMH);
    sgemm_kernel<<<og, 256>>>(xlast, w_out, b_out, (float*)d_out, V, C_OUT, H);
}

// round 16
// speedup vs baseline: 3.0513x; 1.0180x over previous
#include <cuda_runtime.h>
#include <cuda_bf16.h>
#include <cuda_fp16.h>
#include <cstdint>

#define T 8
#define V 10000
#define E 100000
#define C_IN 128
#define H 256
#define DS 16
#define C_OUT 64
#define HD (H * DS)          // 4096
#define TV (T * V)           // 80000

// ---------------------------------------------------------------------------
// Scratch (device globals; no allocation allowed)
// ---------------------------------------------------------------------------
__device__ __align__(128) float g_x0[(size_t)TV * C_IN];
__device__ __align__(128) float g_x1[(size_t)TV * H];
__device__ __align__(128) float g_hT[(size_t)H * TV];   // sage output, [hh][t][v]
__device__ __align__(128) float g_xsr[(size_t)TV * H];
__device__ __align__(128) float g_agg0[(size_t)TV * C_IN];
__device__ __align__(128) float g_agg1[(size_t)TV * H];
__device__ __align__(128) float g_deg[(size_t)TV];
__device__ __align__(128) float g_lam[2 * HD];
__device__ __align__(128) float g_xlast[(size_t)V * H];
__device__ __align__(128) float g_xsrl [(size_t)V * H];
__device__ int g_is64;

// fp16 single-plane transposed weights ([N=256][K], K-major)
__device__ __align__(128) __half g_cat0_f[256 * 256];
__device__ __align__(128) __half g_cat1_f[256 * 512];
__device__ __align__(128) __half g_res0_f[256 * 128];
__device__ __align__(128) __half g_res1_f[256 * 256];
__device__ __align__(128) __half g_mix0_f[256 * HD];
__device__ __align__(128) __half g_mix1_f[256 * HD];

// ---------------------------------------------------------------------------
// Helpers
// ---------------------------------------------------------------------------
__device__ __forceinline__ uint32_t smem_u32(const void* p) {
    uint32_t a;
    asm("{ .reg .u64 t; cvta.to.shared.u64 t, %1; cvt.u32.u64 %0, t; }" : "=r"(a) : "l"(p));
    return a;
}

__device__ __forceinline__ uint32_t pack2h(float a, float b) {
    __half h0 = __float2half_rn(a);
    __half h1 = __float2half_rn(b);
    return (uint32_t)__half_as_ushort(h0) | ((uint32_t)__half_as_ushort(h1) << 16);
}

#define LDSM_X4(r0, r1, r2, r3, addr) \
    asm volatile("ldmatrix.sync.aligned.m8n8.x4.shared.b16 {%0,%1,%2,%3}, [%4];" \
        : "=r"(r0), "=r"(r1), "=r"(r2), "=r"(r3) : "r"(addr))

#define MMA_F16(d, a, b0, b1) \
    asm volatile("mma.sync.aligned.m16n8k16.row.col.f32.f16.f16.f32 " \
        "{%0,%1,%2,%3}, {%4,%5,%6,%7}, {%8,%9}, {%0,%1,%2,%3};" \
        : "+f"((d)[0]), "+f"((d)[1]), "+f"((d)[2]), "+f"((d)[3]) \
        : "r"((a)[0]), "r"((a)[1]), "r"((a)[2]), "r"((a)[3]), "r"(b0), "r"(b1))

#define CP16(dst, src) \
    asm volatile("cp.async.cg.shared.global [%0], [%1], 16;" :: "r"(dst), "l"(src))
#define CP_COMMIT() asm volatile("cp.async.commit_group;" ::: "memory")
#define CP_WAIT0()  asm volatile("cp.async.wait_group 0;" ::: "memory")

// ---------------------------------------------------------------------------
// Small kernels
// ---------------------------------------------------------------------------
// zero three buffers in one launch (agg0, agg1, deg) -- all off critical path
__global__ void zero3_kernel(float4* p1, long long n1, float4* p2, long long n2,
                             float4* p3, long long n3) {
    long long i = blockIdx.x * (long long)blockDim.x + threadIdx.x;
    long long stride = (long long)gridDim.x * blockDim.x;
    const float4 zz = make_float4(0.f, 0.f, 0.f, 0.f);
    for (long long j = i; j < n1; j += stride) p1[j] = zz;
    for (long long j = i; j < n2; j += stride) p2[j] = zz;
    for (long long j = i; j < n3; j += stride) p3[j] = zz;
}

__global__ void detect_kernel(const unsigned int* ei) {
    if (threadIdx.x == 0 && blockIdx.x == 0) {
        unsigned int s = 0;
        for (int i = 0; i < 64; i++) s |= ei[2 * i + 1];
        g_is64 = (s == 0) ? 1 : 0;
    }
}

__device__ __forceinline__ int load_edge(const void* ei, long long pos) {
    if (g_is64) return (int)((const long long*)ei)[pos];
    return ((const int*)ei)[pos];
}

__global__ void lam_kernel(const float* a0, const float* a1, float* lam) {
    int i = blockIdx.x * blockDim.x + threadIdx.x;
    if (i < HD)           lam[i] = expf(-expf(a0[i]));
    else if (i < 2 * HD)  lam[i] = expf(-expf(a1[i - HD]));
}

__global__ void token_mix_kernel(const float* __restrict__ xs,
                                 const float* __restrict__ w,
                                 const float* __restrict__ b,
                                 float* __restrict__ out) {
    int idx = blockIdx.x * blockDim.x + threadIdx.x;
    if (idx >= TV * C_IN) return;
    int c = idx % C_IN;
    int t = idx / (V * C_IN);
    float acc = b[c] + xs[idx] * w[c * 3 + 1];
    if (t > 0)     acc += xs[idx - V * C_IN] * w[c * 3 + 0];
    if (t < T - 1) acc += xs[idx + V * C_IN] * w[c * 3 + 2];
    out[idx] = acc;
}

// ---------------------------------------------------------------------------
// Scatter v2: one thread per (edge, group-lane); GROUP lanes cover the row,
// each lane handles NPASS float4 chunks strided by GROUP (coalesced).
// GROUP*NPASS*4 == C.  deg accumulated once per edge by lane 0.
// ---------------------------------------------------------------------------
template <int GROUP, int NPASS, int C>
__global__ void scatter2_kernel(const float* __restrict__ x, const void* __restrict__ ei,
                                float* __restrict__ agg, float* __restrict__ deg) {
    long long idx = blockIdx.x * (long long)blockDim.x + threadIdx.x;
    long long total = (long long)T * E * GROUP;
    if (idx >= total) return;
    int lane = (int)(idx % GROUP);
    long long te = idx / GROUP;
    int e = (int)(te % E);
    int t = (int)(te / E);
    long long base = (long long)t * 2 * E;
    int src = load_edge(ei, base + e);
    int dst = load_edge(ei, base + E + e);
    const float* xr = &x[((long long)t * V + src) * C];
    float* ar = &agg[((long long)t * V + dst) * C];
#pragma unroll
    for (int p = 0; p < NPASS; p++) {
        int c4 = lane + p * GROUP;
        float4 v = *(const float4*)&xr[c4 * 4];
        asm volatile("red.global.add.v4.f32 [%0], {%1,%2,%3,%4};"
                     :: "l"(&ar[c4 * 4]), "f"(v.x), "f"(v.y), "f"(v.z), "f"(v.w)
                     : "memory");
    }
    if (deg && lane == 0) {
        float* dp = &deg[(long long)t * V + dst];
        asm volatile("red.global.add.f32 [%0], %1;" :: "l"(dp), "f"(1.0f) : "memory");
    }
}

// Build transposed fp16 weights: dst[n][k] = rn(concat(w1,w2)[k][n])
__global__ void f16w_kernel(const float* __restrict__ w1, const float* __restrict__ w2,
                            int K1, int Kt, __half* __restrict__ out) {
    long long idx = blockIdx.x * (long long)blockDim.x + threadIdx.x;
    if (idx >= (long long)Kt * 256) return;
    int k = (int)(idx % Kt);
    int n = (int)(idx / Kt);
    float v = (k < K1) ? w1[(long long)k * 256 + n] : w2[(long long)(k - K1) * 256 + n];
    out[(long long)n * Kt + k] = __float2half_rn(v);
}

// ---------------------------------------------------------------------------
// Shared GEMM geometry constants
// ---------------------------------------------------------------------------
#define ROWB 144                      // 64 k * 2B + 16 pad
#define A_T0 9216                     // 64 * 144
#define B_T0 36864                    // 256 * 144
#define STG0 (A_T0 + B_T0)            // 46080
#define LAM0 (2 * STG0)               // 92160
#define GS_MIX (LAM0 + 32768)         // 124928
#define GS_CAT (2 * STG0)             // 92160

// ---------------------------------------------------------------------------
// MIX kernel (scan-fused, fp16 1-product): tile 64x256 (FULL N), BK=64,
// 512 threads (16 warps 2m x 8n, warp tile 32x32), 1 CTA/SM.
// ---------------------------------------------------------------------------
__global__ __launch_bounds__(512, 1) void mix_kernel(
    const float* __restrict__ hT, const float* __restrict__ lam,
    const float* __restrict__ Bp, int tfix,
    const __half* __restrict__ Bf,
    const float* __restrict__ bias,
    const float* __restrict__ Dadd, long long DzS,
    float* __restrict__ Cout, long long CzS,
    int M, int K)
{
    extern __shared__ char smem[];
    const uint32_t sb = smem_u32(smem);
    const int tid = threadIdx.x;
    const int wid = tid >> 5;
    const int lane = tid & 31;
    const int warp_m = wid >> 3;       // 0..1
    const int warp_n = wid & 7;        // 0..7
    const int z = blockIdx.z;
    const long long m0 = (long long)blockIdx.x * 64;

    const float* Dz = Dadd + (long long)z * DzS;
    float* Cz = Cout + (long long)z * CzS;

    float acc[2][4][4];
#pragma unroll
    for (int i = 0; i < 2; i++)
#pragma unroll
        for (int j = 0; j < 4; j++)
#pragma unroll
            for (int p = 0; p < 4; p++) acc[i][j][p] = 0.f;

    const int nK = K / 64;
    const int ts = (tfix > 0) ? tfix : z + 1;

    const int q = (tid & 255) >> 6;
    const int r = tid & 63;
    const long long rg1 = m0 + r;
    const bool produce = (tid < 256);
    const bool rowok = (rg1 < M);

    float hx[8];

    const uint32_t aoff = (uint32_t)(warp_m * 32 + (lane & 15)) * ROWB +
                          (uint32_t)((lane >> 4) << 3) * 2;
    const uint32_t boff = (uint32_t)(warp_n * 32 + ((lane >> 4) << 3) + (lane & 7)) * ROWB +
                          (uint32_t)(((lane >> 3) & 1) << 3) * 2;

#pragma unroll
    for (int j = 0; j < 2; j++) {
        int idx = tid + 512 * j;       // 0..1023
        *(float4*)(smem + LAM0 + idx * 16)         = ((const float4*)lam)[idx];
        *(float4*)(smem + LAM0 + 16384 + idx * 16) = ((const float4*)Bp)[idx];
    }

    auto cpB = [&](int kt, int stage) {
        const int k0 = kt * 64;
        const uint32_t base = sb + stage * STG0 + A_T0;
#pragma unroll
        for (int i = 0; i < 4; i++) {
            int idx = tid + 512 * i;   // 0..2047
            int n  = idx >> 3;         // 0..255
            int kq = idx & 7;
            uint32_t dst = base + (uint32_t)n * ROWB + (uint32_t)kq * 16;
            long long soff = (long long)n * K + k0 + kq * 8;
            CP16(dst, Bf + soff);
        }
    };

    auto prefA = [&](int kt) {
        if (!produce) return;
        const int hh = (kt * 64 + q * 16) >> 4;
        const long long hb = (long long)hh * TV + rg1;
#pragma unroll
        for (int tt = 0; tt < 8; tt++)
            hx[tt] = (rowok && tt < ts) ? hT[hb + (long long)tt * V] : 0.f;
    };

    auto produceA = [&](int stage, int kt) {
        if (!produce) return;
        const uint32_t off = (uint32_t)stage * STG0 + (uint32_t)r * ROWB + (uint32_t)q * 32;
        const int kg = kt * 64 + q * 16;
        float lam16[16], b16[16];
#pragma unroll
        for (int f = 0; f < 4; f++) {
            *(float4*)&lam16[f * 4] = *(const float4*)(smem + LAM0 + kg * 4 + f * 16);
            *(float4*)&b16[f * 4]   = *(const float4*)(smem + LAM0 + 16384 + kg * 4 + f * 16);
        }
        float s[16];
#pragma unroll
        for (int d = 0; d < 16; d++) s[d] = 0.f;
#pragma unroll
        for (int tt = 0; tt < 8; tt++) {
            if (tt < ts) {
                float x = hx[tt];
#pragma unroll
                for (int d = 0; d < 16; d++) s[d] = lam16[d] * s[d] + x * b16[d];
            }
        }
        uint32_t u[8];
#pragma unroll
        for (int d2 = 0; d2 < 8; d2++)
            u[d2] = pack2h(fmaxf(s[d2 * 2], 0.f), fmaxf(s[d2 * 2 + 1], 0.f));
        *(uint4*)(smem + off)      = make_uint4(u[0], u[1], u[2], u[3]);
        *(uint4*)(smem + off + 16) = make_uint4(u[4], u[5], u[6], u[7]);
    };

    auto compute = [&](int stage) {
        const uint32_t base = sb + stage * STG0;
#pragma unroll
        for (int ks = 0; ks < 4; ks++) {
            const uint32_t kk = (uint32_t)ks * 32;
            uint32_t a_h[2][4];
#pragma unroll
            for (int i = 0; i < 2; i++) {
                uint32_t ad = base + aoff + (uint32_t)(i * 16) * ROWB + kk;
                LDSM_X4(a_h[i][0], a_h[i][1], a_h[i][2], a_h[i][3], ad);
            }
            uint32_t b_h[8];
#pragma unroll
            for (int jj = 0; jj < 2; jj++) {
                uint32_t bd = base + A_T0 + boff + (uint32_t)(jj * 16) * ROWB + kk;
                LDSM_X4(b_h[jj * 4 + 0], b_h[jj * 4 + 1], b_h[jj * 4 + 2], b_h[jj * 4 + 3], bd);
            }
#pragma unroll
            for (int i = 0; i < 2; i++)
#pragma unroll
                for (int j = 0; j < 4; j++)
                    MMA_F16(acc[i][j], a_h[i], b_h[j * 2], b_h[j * 2 + 1]);
        }
    };

    prefA(0);
    cpB(0, 0);
    CP_COMMIT();
    __syncthreads();                   // lam/Bp smem visible
    produceA(0, 0);
    CP_WAIT0();
    __syncthreads();

    for (int kt = 0; kt < nK; kt++) {
        const int cur = kt & 1;
        const bool more = (kt + 1 < nK);
        if (more) {
            prefA(kt + 1);
            cpB(kt + 1, cur ^ 1);
            CP_COMMIT();
        }
        compute(cur);
        if (more) produceA(cur ^ 1, kt + 1);
        CP_WAIT0();
        __syncthreads();
    }

#pragma unroll
    for (int i = 0; i < 2; i++) {
        long long r1 = m0 + warp_m * 32 + i * 16 + (lane >> 2);
        long long r2 = r1 + 8;
#pragma unroll
        for (int j = 0; j < 4; j++) {
            int c = warp_n * 32 + j * 8 + (lane & 3) * 2;
            float2 b2 = *(const float2*)&bias[c];
#pragma unroll
            for (int hh2 = 0; hh2 < 2; hh2++) {
                long long rr = (hh2 == 0) ? r1 : r2;
                if (rr < M) {
                    float vx = acc[i][j][hh2 * 2 + 0] + b2.x;
                    float vy = acc[i][j][hh2 * 2 + 1] + b2.y;
                    float2 d = *(const float2*)&Dz[rr * 256 + c];
                    vx += d.x; vy += d.y;
                    *(float2*)&Cz[rr * 256 + c] = make_float2(vx, vy);
                }
            }
        }
    }
}

// ---------------------------------------------------------------------------
// CAT kernel (fp16 1-product): tile 64x256 (FULL N, grid_y=1 -> A read once),
// BK=64, 512 threads (16 warps 2m x 8n, warp tile 32x32), 1 CTA/SM.
// A[r,k] = rn16(concat(A1, A2*invdeg)[r,k]);  C = A @ Bf^T + bias.
// Optional transposed output Cout[c*CtS + r].
// ---------------------------------------------------------------------------
__global__ __launch_bounds__(512, 1) void cat_kernel(
    const float* __restrict__ A1, const float* __restrict__ A2, int K1,
    const float* __restrict__ deg,
    const __half* __restrict__ Bf,
    const float* __restrict__ bias,
    float* __restrict__ Cout, long long CtS, int trans_out,
    int M, int K)
{
    extern __shared__ char smem[];
    const uint32_t sb = smem_u32(smem);
    const int tid = threadIdx.x;
    const int wid = tid >> 5;
    const int lane = tid & 31;
    const int warp_m = wid >> 3;       // 0..1
    const int warp_n = wid & 7;        // 0..7
    const long long m0 = (long long)blockIdx.x * 64;

    float acc[2][4][4];
#pragma unroll
    for (int i = 0; i < 2; i++)
#pragma unroll
        for (int j = 0; j < 4; j++)
#pragma unroll
            for (int p = 0; p < 4; p++) acc[i][j][p] = 0.f;

    const int nK = K / 64;
    const int q = (tid & 255) >> 6;
    const int r = tid & 63;
    const long long rg1 = m0 + r;
    const bool produce = (tid < 256);
    const bool rowok = (rg1 < M);

    float a16[16];

    const uint32_t aoff = (uint32_t)(warp_m * 32 + (lane & 15)) * ROWB +
                          (uint32_t)((lane >> 4) << 3) * 2;
    const uint32_t boff = (uint32_t)(warp_n * 32 + ((lane >> 4) << 3) + (lane & 7)) * ROWB +
                          (uint32_t)(((lane >> 3) & 1) << 3) * 2;

    auto cpB = [&](int kt, int stage) {
        const int k0 = kt * 64;
        const uint32_t base = sb + stage * STG0 + A_T0;
#pragma unroll
        for (int i = 0; i < 4; i++) {
            int idx = tid + 512 * i;   // 0..2047
            int n  = idx >> 3;         // 0..255
            int kq = idx & 7;
            uint32_t dst = base + (uint32_t)n * ROWB + (uint32_t)kq * 16;
            long long soff = (long long)n * K + k0 + kq * 8;
            CP16(dst, Bf + soff);
        }
    };

    auto prefA = [&](int kt) {
        if (!produce) return;
        const int kg = kt * 64 + q * 16;
        if (rowok) {
            bool second = (kg >= K1);
            const float* src = second ? &A2[rg1 * (long long)(K - K1) + (kg - K1)]
                                      : &A1[rg1 * (long long)K1 + kg];
#pragma unroll
            for (int f = 0; f < 4; f++)
                *(float4*)&a16[f * 4] = ((const float4*)src)[f];
            if (second && deg) {
                float inv = 1.0f / fmaxf(deg[rg1], 1.0f);
#pragma unroll
                for (int d = 0; d < 16; d++) a16[d] *= inv;
            }
        } else {
#pragma unroll
            for (int d = 0; d < 16; d++) a16[d] = 0.f;
        }
    };

    auto produceA = [&](int stage) {
        if (!produce) return;
        const uint32_t off = (uint32_t)stage * STG0 + (uint32_t)r * ROWB + (uint32_t)q * 32;
        uint32_t u[8];
#pragma unroll
        for (int d2 = 0; d2 < 8; d2++)
            u[d2] = pack2h(a16[d2 * 2], a16[d2 * 2 + 1]);
        *(uint4*)(smem + off)      = make_uint4(u[0], u[1], u[2], u[3]);
        *(uint4*)(smem + off + 16) = make_uint4(u[4], u[5], u[6], u[7]);
    };

    auto compute = [&](int stage) {
        const uint32_t base = sb + stage * STG0;
#pragma unroll
        for (int ks = 0; ks < 4; ks++) {
            const uint32_t kk = (uint32_t)ks * 32;
            uint32_t a_h[2][4];
#pragma unroll
            for (int i = 0; i < 2; i++) {
                uint32_t ad = base + aoff + (uint32_t)(i * 16) * ROWB + kk;
                LDSM_X4(a_h[i][0], a_h[i][1], a_h[i][2], a_h[i][3], ad);
            }
            uint32_t b_h[8];
#pragma unroll
            for (int jj = 0; jj < 2; jj++) {
                uint32_t bd = base + A_T0 + boff + (uint32_t)(jj * 16) * ROWB + kk;
                LDSM_X4(b_h[jj * 4 + 0], b_h[jj * 4 + 1], b_h[jj * 4 + 2], b_h[jj * 4 + 3], bd);
            }
#pragma unroll
            for (int i = 0; i < 2; i++)
#pragma unroll
                for (int j = 0; j < 4; j++)
                    MMA_F16(acc[i][j], a_h[i], b_h[j * 2], b_h[j * 2 + 1]);
        }
    };

    prefA(0);
    cpB(0, 0);
    CP_COMMIT();
    produceA(0);
    CP_WAIT0();
    __syncthreads();

    for (int kt = 0; kt < nK; kt++) {
        const int cur = kt & 1;
        const bool more = (kt + 1 < nK);
        if (more) {
            prefA(kt + 1);
            cpB(kt + 1, cur ^ 1);
            CP_COMMIT();
        }
        compute(cur);
        if (more) produceA(cur ^ 1);
        CP_WAIT0();
        __syncthreads();
    }

#pragma unroll
    for (int i = 0; i < 2; i++) {
        long long r1 = m0 + warp_m * 32 + i * 16 + (lane >> 2);
        long long r2 = r1 + 8;
#pragma unroll
        for (int j = 0; j < 4; j++) {
            int c = warp_n * 32 + j * 8 + (lane & 3) * 2;
            float2 b2 = *(const float2*)&bias[c];
#pragma unroll
            for (int hh2 = 0; hh2 < 2; hh2++) {
                long long rr = (hh2 == 0) ? r1 : r2;
                if (rr < M) {
                    float vx = acc[i][j][hh2 * 2 + 0] + b2.x;
                    float vy = acc[i][j][hh2 * 2 + 1] + b2.y;
                    if (trans_out) {
                        Cout[(long long)c * CtS + rr]       = vx;
                        Cout[(long long)(c + 1) * CtS + rr] = vy;
                    } else {
                        *(float2*)&Cout[rr * 256 + c] = make_float2(vx, vy);
                    }
                }
            }
        }
    }
}

// ---------------------------------------------------------------------------
// fp32 SGEMM for the small output head (N=64)
// ---------------------------------------------------------------------------
#define BMH 128
#define BNH 128
#define BKH 8

__global__ __launch_bounds__(256) void sgemm_kernel(
    const float* __restrict__ A, const float* __restrict__ B,
    const float* __restrict__ bias, float* __restrict__ C, int M, int N, int K)
{
    __shared__ float As[BKH][BMH];
    __shared__ float Bs[BKH][BNH];
    int row0 = blockIdx.y * BMH;
    int col0 = blockIdx.x * BNH;
    int tid = threadIdx.x;
    int aRow = tid >> 1;
    int aCol = (tid & 1) * 4;
    int bRow = tid >> 5;
    int bCol = (tid & 31) * 4;
    int tx = tid & 15;
    int ty = tid >> 4;
    float acc[8][8];
#pragma unroll
    for (int i = 0; i < 8; i++)
#pragma unroll
        for (int j = 0; j < 8; j++) acc[i][j] = 0.f;
    int nK = K / BKH;
    for (int kt = 0; kt < nK; ++kt) {
        int k0 = kt * BKH;
        float4 av = make_float4(0.f, 0.f, 0.f, 0.f);
        int gr = row0 + aRow;
        if (gr < M) av = *(const float4*)&A[(long long)gr * K + k0 + aCol];
        As[aCol + 0][aRow] = av.x;
        As[aCol + 1][aRow] = av.y;
        As[aCol + 2][aRow] = av.z;
        As[aCol + 3][aRow] = av.w;
        float4 bv = make_float4(0.f, 0.f, 0.f, 0.f);
        int gc = col0 + bCol;
        if (gc < N) bv = *(const float4*)&B[(long long)(k0 + bRow) * N + gc];
        *(float4*)&Bs[bRow][bCol] = bv;
        __syncthreads();
#pragma unroll
        for (int k = 0; k < BKH; k++) {
            float ar[8], br[8];
#pragma unroll
            for (int i = 0; i < 8; i++) ar[i] = As[k][ty * 8 + i];
#pragma unroll
            for (int j = 0; j < 8; j++) br[j] = Bs[k][tx * 8 + j];
#pragma unroll
            for (int i = 0; i < 8; i++)
#pragma unroll
                for (int j = 0; j < 8; j++) acc[i][j] += ar[i] * br[j];
        }
        __syncthreads();
    }
#pragma unroll
    for (int i = 0; i < 8; i++) {
        int r = row0 + ty * 8 + i;
        if (r >= M) continue;
#pragma unroll
        for (int j = 0; j < 8; j++) {
            int c = col0 + tx * 8 + j;
            if (c >= N) continue;
            C[(long long)r * N + c] = acc[i][j] + bias[c];
        }
    }
}

// ---------------------------------------------------------------------------
// Host helpers
// ---------------------------------------------------------------------------
static void gemm_cat(const float* A1, const float* A2, int K1, const float* deg,
                     const __half* Bf,
                     const float* bias, float* C, long long CtS, int trans,
                     int M, int K) {
    dim3 grid((M + 63) / 64, 1, 1);
    cat_kernel<<<grid, 512, GS_CAT>>>(A1, A2, K1, deg, Bf, bias, C, CtS, trans, M, K);
}

static void gemm_mix(const float* hT, const float* lam, const float* Bp, int tfix,
                     const __half* Bf,
                     const float* bias, const float* Dadd, long long DzS,
                     float* C, long long CzS, int M, int K, int nz) {
    dim3 grid((M + 63) / 64, 1, nz);
    mix_kernel<<<grid, 512, GS_MIX>>>(hT, lam, Bp, tfix, Bf, bias, Dadd, DzS,
                                      C, CzS, M, K);
}

// ---------------------------------------------------------------------------
// Launch
// ---------------------------------------------------------------------------
extern "C" void kernel_launch(void* const* d_in, const int* in_sizes, int n_in,
                              void* d_out, int out_size) {
    const float* xs      = (const float*)d_in[0];
    const void*  ei      = d_in[1];
    const float* w_pre   = (const float*)d_in[2];
    const float* b_pre   = (const float*)d_in[3];

    const float* w_res0  = (const float*)d_in[4];
    const float* b_res0  = (const float*)d_in[5];
    const float* w_self0 = (const float*)d_in[6];
    const float* w_neigh0= (const float*)d_in[7];
    const float* b_sage0 = (const float*)d_in[8];
    const float* a_log0  = (const float*)d_in[9];
    const float* B0      = (const float*)d_in[10];
    const float* w_mix0  = (const float*)d_in[11];
    const float* b_mix0  = (const float*)d_in[12];

    const float* w_res1  = (const float*)d_in[13];
    const float* b_res1  = (const float*)d_in[14];
    const float* w_self1 = (const float*)d_in[15];
    const float* w_neigh1= (const float*)d_in[16];
    const float* b_sage1 = (const float*)d_in[17];
    const float* a_log1  = (const float*)d_in[18];
    const float* B1      = (const float*)d_in[19];
    const float* w_mix1  = (const float*)d_in[20];
    const float* b_mix1  = (const float*)d_in[21];

    const float* w_out   = (const float*)d_in[22];
    const float* b_out   = (const float*)d_in[23];

    float *x0, *x1, *hT, *xsr, *agg0, *agg1, *deg, *lam, *xlast, *xsrl;
    cudaGetSymbolAddress((void**)&x0,    g_x0);
    cudaGetSymbolAddress((void**)&x1,    g_x1);
    cudaGetSymbolAddress((void**)&hT,    g_hT);
    cudaGetSymbolAddress((void**)&xsr,   g_xsr);
    cudaGetSymbolAddress((void**)&agg0,  g_agg0);
    cudaGetSymbolAddress((void**)&agg1,  g_agg1);
    cudaGetSymbolAddress((void**)&deg,   g_deg);
    cudaGetSymbolAddress((void**)&lam,   g_lam);
    cudaGetSymbolAddress((void**)&xlast, g_xlast);
    cudaGetSymbolAddress((void**)&xsrl,  g_xsrl);

    __half *cat0f, *cat1f, *res0f, *res1f, *mix0f, *mix1f;
    cudaGetSymbolAddress((void**)&cat0f, g_cat0_f);
    cudaGetSymbolAddress((void**)&cat1f, g_cat1_f);
    cudaGetSymbolAddress((void**)&res0f, g_res0_f);
    cudaGetSymbolAddress((void**)&res1f, g_res1_f);
    cudaGetSymbolAddress((void**)&mix0f, g_mix0_f);
    cudaGetSymbolAddress((void**)&mix1f, g_mix1_f);

    cudaFuncSetAttribute(mix_kernel,
                         cudaFuncAttributeMaxDynamicSharedMemorySize, GS_MIX);
    cudaFuncSetAttribute(cat_kernel,
                         cudaFuncAttributeMaxDynamicSharedMemorySize, GS_CAT);

    auto fw = [](const float* w1, const float* w2, int K1, int Kt, __half* out) {
        long long tot = (long long)Kt * 256;
        f16w_kernel<<<(int)((tot + 255) / 256), 256>>>(w1, w2, K1, Kt, out);
    };

    detect_kernel<<<1, 32>>>((const unsigned int*)ei);
    lam_kernel<<<(2 * HD + 255) / 256, 256>>>(a_log0, a_log1, lam);
    token_mix_kernel<<<(TV * C_IN + 255) / 256, 256>>>(xs, w_pre, b_pre, x0);
    // zero agg0, agg1, deg all at once (agg1 zeroing off the critical path)
    zero3_kernel<<<1024, 256>>>((float4*)agg0, (long long)TV * C_IN / 4,
                                (float4*)agg1, (long long)TV * H / 4,
                                (float4*)deg,  (long long)TV / 4);
    {
        // layer-0 scatter: GROUP=8, NPASS=4 (C=128)
        long long tot = (long long)T * E * 8;
        scatter2_kernel<8, 4, C_IN><<<(int)((tot + 255) / 256), 256>>>(x0, ei, agg0, deg);
    }
    fw(w_self0, w_neigh0, C_IN, 2 * C_IN, cat0f);
    fw(w_self1, w_neigh1, H, 2 * H, cat1f);
    fw(w_res0, nullptr, C_IN, C_IN, res0f);
    fw(w_res1, nullptr, H, H, res1f);
    fw(w_mix0, nullptr, HD, HD, mix0f);
    fw(w_mix1, nullptr, HD, HD, mix1f);

    // ---------------- layer 0 ----------------
    gemm_cat(x0, agg0, C_IN, deg, cat0f, b_sage0, hT, TV, 1, TV, 2 * C_IN);
    gemm_cat(x0, x0,  C_IN, nullptr, res0f, b_res0, xsr, 0, 0, TV, C_IN);

    // all 8 mix0 GEMMs, scan fused in producer (ts = z+1), full-N tile
    gemm_mix(hT, lam, B0, 0, mix0f, b_mix0,
             xsr, (long long)V * H, x1, (long long)V * H, V, HD, T);

    // ---------------- layer 1 ----------------
    {
        // layer-1 scatter: GROUP=8, NPASS=8 (C=256)
        long long tot = (long long)T * E * 8;
        scatter2_kernel<8, 8, H><<<(int)((tot + 255) / 256), 256>>>(x1, ei, agg1, nullptr);
    }
    gemm_cat(x1, agg1, H, deg, cat1f, b_sage1, hT, TV, 1, TV, 2 * H);
    gemm_cat(x1 + (long long)(T - 1) * V * H, x1 + (long long)(T - 1) * V * H, H,
             nullptr, res1f, b_res1, xsrl, 0, 0, V, H);

    // mix1: full 8-step scan, single z (xsrl as Dadd slot 0)
    gemm_mix(hT, lam + HD, B1, T, mix1f, b_mix1,
             xsrl, 0, xlast, 0, V, HD, 1);

    // ---------------- output head ----------------
    dim3 og((C_OUT + BNH - 1) / BNH, (V + BMH - 1) / BMH);
    sgemm_kernel<<<og, 256>>>(xlast, w_out, b_out, (float*)d_out, V, C_OUT, H);
}